// round 15
// baseline (speedup 1.0000x reference)
#include <cuda_runtime.h>
#include <math.h>
#include <stdint.h>

#define B 2
#define D 768
#define H 16
#define HD 48
#define L 3
#define N_IMG 1024
#define N_PAST 16
#define T_DEC 20
#define S0 (N_IMG + 1 + N_PAST)    // 1041
#define SMAX (S0 + T_DEC)          // 1061
#define M0 (B * S0)                // 2082
#define D3 (3 * D)                 // 2304
#define DFF (4 * D)                // 3072
#define CACHE_L (B * H * SMAX * HD)
#define NSPLIT 4

#define ATT_SCALE 0.14433756729740643f  // 1/sqrt(48)

// ------------------------- static device scratch -------------------------
__device__ float g_x[M0 * D];
__device__ float g_h[M0 * D];
__device__ float g_qkv[M0 * D3];
__device__ float g_ff[M0 * DFF];
__device__ float g_ctx[M0 * D];
__device__ float g_K[L * CACHE_L];
__device__ float g_V[L * CACHE_L];
__device__ float g_xvec[B * D];
__device__ float g_qvec[B * D];
__device__ float g_fvec[B * DFF];
__device__ float g_gvec[B * D];
__device__ float g_part[48 * 2 * 2304];   // max KS*2*N = 48*2*768 and 16*2*2304 etc; sized generously
__device__ float g_attA[B * H * NSPLIT * HD];
__device__ float g_attM[B * H * NSPLIT];
__device__ float g_attL[B * H * NSPLIT];
__device__ unsigned g_barcnt;

__device__ __forceinline__ float gelu_exact(float x) {
    return 0.5f * x * (1.0f + erff(x * 0.7071067811865475f));
}

__device__ __forceinline__ uint32_t f2tf32(float x) {
    uint32_t r;
    asm("cvt.rna.tf32.f32 %0, %1;" : "=r"(r) : "f"(x));
    return r;
}

__device__ __forceinline__ void mma_tf32(float* c, const uint32_t* a,
                                         uint32_t b0, uint32_t b1) {
    asm("mma.sync.aligned.m16n8k8.row.col.f32.tf32.tf32.f32 "
        "{%0,%1,%2,%3}, {%4,%5,%6,%7}, {%8,%9}, {%0,%1,%2,%3};"
        : "+f"(c[0]), "+f"(c[1]), "+f"(c[2]), "+f"(c[3])
        : "r"(a[0]), "r"(a[1]), "r"(a[2]), "r"(a[3]), "r"(b0), "r"(b1));
}

// ------------------------- embed -------------------------
__global__ void embed_kernel(const float* __restrict__ feats,
                             const float* __restrict__ img_pos,
                             const int* __restrict__ intent,
                             const float* __restrict__ int_emb,
                             const float* __restrict__ past,
                             const float* __restrict__ past_W,
                             const float* __restrict__ past_b,
                             const float* __restrict__ time_emb,
                             float* __restrict__ X) {
    int idx = blockIdx.x * blockDim.x + threadIdx.x;
    if (idx >= B * S0 * D) return;
    int d = idx % D;
    int s = (idx / D) % S0;
    int b = idx / (D * S0);
    float v;
    if (s < N_IMG) {
        v = feats[((size_t)b * D + d) * N_IMG + s] + img_pos[(size_t)s * D + d];
    } else if (s == N_IMG) {
        int ii = intent[b] - 1;
        ii = ii < 0 ? 0 : (ii > 2 ? 2 : ii);
        v = int_emb[ii * D + d];
    } else {
        int j = s - N_IMG - 1;
        v = past_b[d] + time_emb[j * D + d];
        #pragma unroll
        for (int c = 0; c < 6; c++)
            v += past[(b * N_PAST + j) * 6 + c] * past_W[c * D + d];
    }
    X[idx] = v;
}

// ------------------------- layernorm (prefill) -------------------------
__global__ void ln_kernel(const float* __restrict__ X, float* __restrict__ Y,
                          const float* __restrict__ gam, const float* __restrict__ bet) {
    int row = blockIdx.x;
    const float* x = X + (size_t)row * D;
    float* y = Y + (size_t)row * D;
    __shared__ float red[256];
    int t = threadIdx.x;
    float s = 0.f;
    for (int i = t; i < D; i += 256) s += x[i];
    red[t] = s; __syncthreads();
    for (int o = 128; o > 0; o >>= 1) { if (t < o) red[t] += red[t + o]; __syncthreads(); }
    float mean = red[0] * (1.0f / D);
    __syncthreads();
    float vs = 0.f;
    for (int i = t; i < D; i += 256) { float dd = x[i] - mean; vs += dd * dd; }
    red[t] = vs; __syncthreads();
    for (int o = 128; o > 0; o >>= 1) { if (t < o) red[t] += red[t + o]; __syncthreads(); }
    float inv = rsqrtf(red[0] * (1.0f / D) + 1e-5f);
    for (int i = t; i < D; i += 256)
        y[i] = (x[i] - mean) * inv * gam[i] + bet[i];
}

// ------------------------- tf32 tensor-core GEMM (R12-proven) -------------------------
#define TM 128
#define TN 128
#define TK 16
__global__ void __launch_bounds__(256)
gemm_kernel(const float* __restrict__ A, const float* __restrict__ W,
            const float* __restrict__ bias, const float* __restrict__ R,
            float* __restrict__ C, int M, int N, int K, int act) {
    __shared__ float As[TK][136];
    __shared__ float Ws[TK][136];
    int tid = threadIdx.x;
    int warp = tid >> 5, lane = tid & 31;
    int wm = warp & 1, wn = warp >> 1;
    int wrow = wm * 64, wcol = wn * 32;
    int row0 = blockIdx.y * TM, col0 = blockIdx.x * TN;
    int lq = lane >> 2, lr = lane & 3;

    float acc[4][4][4];
    #pragma unroll
    for (int i = 0; i < 4; i++)
        #pragma unroll
        for (int j = 0; j < 4; j++)
            #pragma unroll
            for (int r = 0; r < 4; r++) acc[i][j][r] = 0.f;

    for (int k0 = 0; k0 < K; k0 += TK) {
        #pragma unroll
        for (int i = 0; i < 2; i++) {
            int idx = tid * 2 + i;
            int r = idx >> 2, c4 = idx & 3;
            int gm = row0 + r;
            float4 v = make_float4(0.f, 0.f, 0.f, 0.f);
            if (gm < M) v = *reinterpret_cast<const float4*>(&A[(size_t)gm * K + k0 + c4 * 4]);
            As[c4 * 4 + 0][r] = v.x;
            As[c4 * 4 + 1][r] = v.y;
            As[c4 * 4 + 2][r] = v.z;
            As[c4 * 4 + 3][r] = v.w;
        }
        #pragma unroll
        for (int i = 0; i < 2; i++) {
            int idx = tid * 2 + i;
            int kk = idx >> 5, c4 = idx & 31;
            float4 v = *reinterpret_cast<const float4*>(&W[(size_t)(k0 + kk) * N + col0 + c4 * 4]);
            Ws[kk][c4 * 4 + 0] = v.x;
            Ws[kk][c4 * 4 + 1] = v.y;
            Ws[kk][c4 * 4 + 2] = v.z;
            Ws[kk][c4 * 4 + 3] = v.w;
        }
        __syncthreads();

        #pragma unroll
        for (int ks = 0; ks < 2; ks++) {
            int kb = ks * 8;
            uint32_t afr[4][4];
            #pragma unroll
            for (int ma = 0; ma < 4; ma++) {
                int r = wrow + ma * 16 + lq;
                int kk = kb + lr;
                afr[ma][0] = f2tf32(As[kk][r]);
                afr[ma][1] = f2tf32(As[kk][r + 8]);
                afr[ma][2] = f2tf32(As[kk + 4][r]);
                afr[ma][3] = f2tf32(As[kk + 4][r + 8]);
            }
            #pragma unroll
            for (int na = 0; na < 4; na++) {
                int n = wcol + na * 8 + lq;
                int kk = kb + lr;
                uint32_t b0 = f2tf32(Ws[kk][n]);
                uint32_t b1 = f2tf32(Ws[kk + 4][n]);
                #pragma unroll
                for (int ma = 0; ma < 4; ma++)
                    mma_tf32(acc[ma][na], afr[ma], b0, b1);
            }
        }
        __syncthreads();
    }

    #pragma unroll
    for (int ma = 0; ma < 4; ma++) {
        #pragma unroll
        for (int half = 0; half < 2; half++) {
            int gm = row0 + wrow + ma * 16 + lq + half * 8;
            if (gm >= M) continue;
            #pragma unroll
            for (int na = 0; na < 4; na++) {
                int gn = col0 + wcol + na * 8 + 2 * lr;
                float v0 = acc[ma][na][half * 2 + 0] + bias[gn];
                float v1 = acc[ma][na][half * 2 + 1] + bias[gn + 1];
                if (R) {
                    v0 += R[(size_t)gm * N + gn];
                    v1 += R[(size_t)gm * N + gn + 1];
                }
                if (act == 1) { v0 = fmaxf(v0, 0.f); v1 = fmaxf(v1, 0.f); }
                C[(size_t)gm * N + gn]     = v0;
                C[(size_t)gm * N + gn + 1] = v1;
            }
        }
    }
}

// ------------------------- scatter prefill K,V -------------------------
__global__ void scatter_kv(const float* __restrict__ qkv,
                           float* __restrict__ Kc, float* __restrict__ Vc) {
    int idx = blockIdx.x * blockDim.x + threadIdx.x;
    if (idx >= B * S0 * D) return;
    int e = idx % D;
    int s = (idx / D) % S0;
    int b = idx / (D * S0);
    int h = e / HD, ee = e % HD;
    size_t dst = (((size_t)(b * H + h)) * SMAX + s) * HD + ee;
    size_t src = ((size_t)(b * S0 + s)) * D3;
    Kc[dst] = qkv[src + D + e];
    Vc[dst] = qkv[src + 2 * D + e];
}

// ------------------------- prefill attention -------------------------
__global__ void attn_prefill(const float* __restrict__ QKV,
                             const float* __restrict__ Kc,
                             const float* __restrict__ Vc,
                             float* __restrict__ O) {
    int bh = blockIdx.y;
    int b = bh / H, h = bh % H;
    int q0 = blockIdx.x * 4;
    int warp = threadIdx.x >> 5, lane = threadIdx.x & 31;
    int qrow = q0 + warp;
    if (qrow >= S0) qrow = S0 - 1;

    __shared__ float qs[4][HD];
    __shared__ float Ks[32][49];
    __shared__ float Vs[32][49];

    {
        size_t qb = ((size_t)(b * S0 + qrow)) * D3 + h * HD;
        qs[warp][lane] = QKV[qb + lane];
        if (lane < 16) qs[warp][32 + lane] = QKV[qb + 32 + lane];
    }
    __syncthreads();

    int jmax_blk = q0 + 3; if (jmax_blk >= S0) jmax_blk = S0 - 1;
    size_t kvbase = (size_t)bh * SMAX * HD;

    float mrun = -INFINITY, srun = 0.f, acc0 = 0.f, acc1 = 0.f;

    for (int j0 = 0; j0 <= jmax_blk; j0 += 32) {
        for (int i = threadIdx.x; i < 32 * HD; i += 128) {
            int r = i / HD, c = i % HD;
            int j = j0 + r;
            float kv = 0.f, vv = 0.f;
            if (j < S0) {
                kv = Kc[kvbase + (size_t)j * HD + c];
                vv = Vc[kvbase + (size_t)j * HD + c];
            }
            Ks[r][c] = kv; Vs[r][c] = vv;
        }
        __syncthreads();

        int j = j0 + lane;
        float s = -INFINITY;
        if (j <= qrow) {
            s = 0.f;
            #pragma unroll
            for (int d = 0; d < HD; d++) s += qs[warp][d] * Ks[lane][d];
            s *= ATT_SCALE;
        }
        float cm = s;
        #pragma unroll
        for (int o = 16; o > 0; o >>= 1) cm = fmaxf(cm, __shfl_xor_sync(0xffffffffu, cm, o));
        float mnew = fmaxf(mrun, cm);
        float corr = expf(mrun - mnew);
        float p = (j <= qrow) ? expf(s - mnew) : 0.f;
        float ps = p;
        #pragma unroll
        for (int o = 16; o > 0; o >>= 1) ps += __shfl_xor_sync(0xffffffffu, ps, o);
        srun = srun * corr + ps;
        mrun = mnew;
        acc0 *= corr; acc1 *= corr;
        #pragma unroll 4
        for (int src = 0; src < 32; src++) {
            float pp = __shfl_sync(0xffffffffu, p, src);
            acc0 += pp * Vs[src][lane];
            if (lane < 16) acc1 += pp * Vs[src][32 + lane];
        }
        __syncthreads();
    }

    if (q0 + warp < S0) {
        float inv = 1.f / srun;
        size_t ob = ((size_t)(b * S0 + qrow)) * D + h * HD;
        O[ob + lane] = acc0 * inv;
        if (lane < 16) O[ob + 32 + lane] = acc1 * inv;
    }
}

__global__ void copy_last(const float* __restrict__ X, float* __restrict__ xv) {
    int idx = blockIdx.x * blockDim.x + threadIdx.x;
    if (idx >= B * D) return;
    int b = idx / D, d = idx % D;
    xv[idx] = X[((size_t)(b * S0 + S0 - 1)) * D + d];
}

__global__ void reset_bar_kernel() { g_barcnt = 0u; }

// ===================== decode MEGAKERNEL (R13-proven) with rebalanced split-K =====================
#define AP_PLAIN 0
#define AP_LN    1
#define AP_ATT   2

__device__ __forceinline__ void gbar(int& cnt) {
    cnt++;
    __threadfence();
    __syncthreads();
    if (threadIdx.x == 0) {
        atomicAdd(&g_barcnt, 1u);
        unsigned target = (unsigned)cnt * gridDim.x;
        while (*(volatile unsigned*)&g_barcnt < target) { __nanosleep(64); }
    }
    __syncthreads();
    __threadfence();
}

__device__ void stage_part(int bx, int by,
                           const float* Avec, const float* W, float* part,
                           int N, int K, int KS, int mode,
                           const float* gam, const float* bet,
                           const float* attA, const float* attM, const float* attL,
                           float (*Asl)[192], float* red, float* red2) {
    int t = threadIdx.x;
    int len = K / KS;
    int k0 = by * len;

    if (mode == AP_PLAIN) {
        for (int i = t; i < 2 * len; i += 256) {
            int m = i / len, kk = i % len;
            Asl[m][kk] = __ldcg(Avec + m * K + k0 + kk);
        }
    } else if (mode == AP_LN) {
        float mean[2], inv[2];
        #pragma unroll
        for (int m = 0; m < 2; m++) {
            float s = 0.f, ss = 0.f;
            for (int i = t; i < K; i += 256) {
                float v = __ldcg(Avec + m * K + i);
                s += v; ss += v * v;
            }
            red[t] = s; red2[t] = ss; __syncthreads();
            for (int o = 128; o > 0; o >>= 1) {
                if (t < o) { red[t] += red[t + o]; red2[t] += red2[t + o]; }
                __syncthreads();
            }
            mean[m] = red[0] * (1.0f / D);
            inv[m] = rsqrtf(red2[0] * (1.0f / D) - mean[m] * mean[m] + 1e-5f);
            __syncthreads();
        }
        for (int i = t; i < 2 * len; i += 256) {
            int m = i / len, kk = i % len;
            int gk = k0 + kk;
            Asl[m][kk] = (__ldcg(Avec + m * K + gk) - mean[m]) * inv[m] * gam[gk] + bet[gk];
        }
    } else { // AP_ATT
        for (int i = t; i < 2 * len; i += 256) {
            int m = i / len, e = k0 + i % len;
            int h = e / HD, d = e % HD;
            int bh = m * H + h;
            float M = -INFINITY;
            #pragma unroll
            for (int s = 0; s < NSPLIT; s++) M = fmaxf(M, __ldcg(attM + bh * NSPLIT + s));
            float num = 0.f, den = 0.f;
            #pragma unroll
            for (int s = 0; s < NSPLIT; s++) {
                float w = expf(__ldcg(attM + bh * NSPLIT + s) - M);
                num += w * __ldcg(attA + (bh * NSPLIT + s) * HD + d);
                den += w * __ldcg(attL + bh * NSPLIT + s);
            }
            Asl[m][i % len] = num / den;
        }
    }
    __syncthreads();

    int n = bx * 256 + t;
    const float* Wp = W + (size_t)k0 * N + n;
    float a0 = 0.f, a1 = 0.f;
    #pragma unroll 8
    for (int kk = 0; kk < len; kk++) {
        float w = *Wp; Wp += N;
        a0 += Asl[0][kk] * w;
        a1 += Asl[1][kk] * w;
    }
    __stcg(part + (by * 2 + 0) * N + n, a0);
    __stcg(part + (by * 2 + 1) * N + n, a1);
}

__device__ void stage_fin(int bx, const float* part, const float* bias,
                          const float* Res, float* dst,
                          int N, int KS, int act, int scatter, int s_new,
                          float* Kc, float* Vc, float* qv) {
    int n = bx * 256 + threadIdx.x;
    float a0 = bias[n], a1 = a0;
    for (int ks = 0; ks < KS; ks++) {
        a0 += __ldcg(part + (ks * 2 + 0) * N + n);
        a1 += __ldcg(part + (ks * 2 + 1) * N + n);
    }
    if (Res) { a0 += __ldcg(Res + n); a1 += __ldcg(Res + N + n); }
    if (act == 1) { a0 = fmaxf(a0, 0.f); a1 = fmaxf(a1, 0.f); }
    else if (act == 2) { a0 = gelu_exact(a0); a1 = gelu_exact(a1); }
    if (scatter == 0) {
        __stcg(dst + n, a0); __stcg(dst + N + n, a1);
    } else {
        if (n < D) {
            __stcg(qv + n, a0); __stcg(qv + D + n, a1);
        } else if (n < 2 * D) {
            int e = n - D; int h = e / HD, ee = e % HD;
            __stcg(Kc + ((size_t)h * SMAX + s_new) * HD + ee, a0);
            __stcg(Kc + ((size_t)(H + h) * SMAX + s_new) * HD + ee, a1);
        } else {
            int e = n - 2 * D; int h = e / HD, ee = e % HD;
            __stcg(Vc + ((size_t)h * SMAX + s_new) * HD + ee, a0);
            __stcg(Vc + ((size_t)(H + h) * SMAX + s_new) * HD + ee, a1);
        }
    }
}

__device__ void stage_attn(int bh, int split,
                           const float* qv, const float* Kc, const float* Vc, int Slen,
                           float* attA, float* attM, float* attL,
                           float* qs, float* sc, float* red, float* pvred) {
    int b = bh / H, h = bh % H;
    int len = (Slen + NSPLIT - 1) / NSPLIT;
    int j0 = split * len;
    int j1 = min(j0 + len, Slen);
    int cnt = j1 - j0;
    int t = threadIdx.x;
    if (t < HD) qs[t] = __ldcg(qv + b * D + h * HD + t);
    __syncthreads();

    size_t base = (size_t)bh * SMAX * HD;
    float lmax = -INFINITY;
    for (int jl = t; jl < cnt; jl += 256) {
        const float* kp = Kc + base + (size_t)(j0 + jl) * HD;
        float s = 0.f;
        #pragma unroll
        for (int d = 0; d < HD; d++) s += qs[d] * __ldcg(kp + d);
        s *= ATT_SCALE;
        sc[jl] = s;
        lmax = fmaxf(lmax, s);
    }
    red[t] = lmax; __syncthreads();
    for (int o = 128; o > 0; o >>= 1) { if (t < o) red[t] = fmaxf(red[t], red[t + o]); __syncthreads(); }
    float m = red[0];
    __syncthreads();
    float ls = 0.f;
    for (int jl = t; jl < cnt; jl += 256) {
        float p = expf(sc[jl] - m);
        sc[jl] = p;
        ls += p;
    }
    red[t] = ls; __syncthreads();
    for (int o = 128; o > 0; o >>= 1) { if (t < o) red[t] += red[t + o]; __syncthreads(); }
    float l = red[0];
    __syncthreads();

    if (t < 5 * HD) {
        int d = t % HD, g = t / HD;
        float a = 0.f;
        for (int jl = g; jl < cnt; jl += 5)
            a += sc[jl] * __ldcg(Vc + base + (size_t)(j0 + jl) * HD + d);
        pvred[g * HD + d] = a;
    }
    __syncthreads();
    if (t < HD) {
        float a = pvred[t] + pvred[HD + t] + pvred[2 * HD + t] + pvred[3 * HD + t] + pvred[4 * HD + t];
        __stcg(attA + (bh * NSPLIT + split) * HD + t, a);
        if (t == 0) {
            __stcg(attM + bh * NSPLIT + split, m);
            __stcg(attL + bh * NSPLIT + split, l);
        }
    }
    __syncthreads();
}

__device__ void stage_head2(int b, const float* gvec,
                            const float* dec2_W, const float* dec2_b,
                            const float* pos_W, const float* pos_b,
                            const float* time_emb, int t_step,
                            float* out, float* xv, float* r0, float* r1) {
    int tid = threadIdx.x;
    float p0 = 0.f, p1 = 0.f;
    for (int k = tid; k < D; k += 256) {
        float g = __ldcg(gvec + b * D + k);
        p0 += g * dec2_W[k * 2];
        p1 += g * dec2_W[k * 2 + 1];
    }
    r0[tid] = p0; r1[tid] = p1; __syncthreads();
    for (int o = 128; o > 0; o >>= 1) {
        if (tid < o) { r0[tid] += r0[tid + o]; r1[tid] += r1[tid + o]; }
        __syncthreads();
    }
    p0 = r0[0] + dec2_b[0];
    p1 = r1[0] + dec2_b[1];
    if (tid == 0) {
        __stcg(out + (b * T_DEC + t_step) * 2 + 0, p0);
        __stcg(out + (b * T_DEC + t_step) * 2 + 1, p1);
    }
    for (int d = tid; d < D; d += 256)
        __stcg(xv + b * D + d,
               p0 * pos_W[d] + p1 * pos_W[D + d] + pos_b[d]
               + time_emb[(N_PAST + t_step) * D + d]);
    __syncthreads();
}

__global__ void __launch_bounds__(256)
decode_mega(const float* __restrict__ qkv_W, const float* __restrict__ qkv_b,
            const float* __restrict__ out_W, const float* __restrict__ out_b,
            const float* __restrict__ ff1_W, const float* __restrict__ ff1_b,
            const float* __restrict__ ff2_W, const float* __restrict__ ff2_b,
            const float* __restrict__ ln1_g, const float* __restrict__ ln1_b,
            const float* __restrict__ ln2_g, const float* __restrict__ ln2_b,
            const float* __restrict__ dec1_W, const float* __restrict__ dec1_b,
            const float* __restrict__ dec2_W, const float* __restrict__ dec2_b,
            const float* __restrict__ pos_W, const float* __restrict__ pos_b,
            const float* __restrict__ time_emb,
            float* __restrict__ xv, float* __restrict__ qv,
            float* __restrict__ fv, float* __restrict__ gv,
            float* __restrict__ part,
            float* __restrict__ Kc, float* __restrict__ Vc,
            float* __restrict__ attA, float* __restrict__ attM,
            float* __restrict__ attL, float* __restrict__ out) {
    __shared__ float Asl[2][192];
    __shared__ float red[256], red2[256];
    __shared__ float sc[272], pvred[5 * HD], qs[64];

    int bid = blockIdx.x;
    int cnt = 0;

    for (int t = 0; t < T_DEC; t++) {
        // dec1_part: (3, 48) = 144 tasks, len=16
        if (bid < 144) stage_part(bid % 3, bid / 3, xv, dec1_W, part, D, D, 48, AP_PLAIN,
                                  nullptr, nullptr, nullptr, nullptr, nullptr, Asl, red, red2);
        gbar(cnt);
        // dec1_fin (gelu -> gv): 3 tasks, KS=48
        if (bid < 3) stage_fin(bid, part, dec1_b, nullptr, gv, D, 48, 2, 0, 0,
                               nullptr, nullptr, nullptr);
        gbar(cnt);
        // head2: 2 tasks
        if (bid < 2) stage_head2(bid, gv, dec2_W, dec2_b, pos_W, pos_b, time_emb,
                                 t, out, xv, red, red2);
        gbar(cnt);

        if (t == T_DEC - 1) break;
        int s_new = S0 + t;

        for (int l = 0; l < L; l++) {
            float* Kl = Kc + (size_t)l * CACHE_L;
            float* Vl = Vc + (size_t)l * CACHE_L;

            // qkv_part: (9, 16) = 144, len=48
            if (bid < 144) stage_part(bid % 9, bid / 9, xv, qkv_W + (size_t)l * D * D3, part,
                                      D3, D, 16, AP_LN, ln1_g + l * D, ln1_b + l * D,
                                      nullptr, nullptr, nullptr, Asl, red, red2);
            gbar(cnt);
            // qkv_fin (scatter): 9, KS=16
            if (bid < 9) stage_fin(bid, part, qkv_b + l * D3, nullptr, nullptr,
                                   D3, 16, 0, 1, s_new, Kl, Vl, qv);
            gbar(cnt);
            // attn: (32,4) = 128
            if (bid < 128) stage_attn(bid & 31, bid >> 5, qv, Kl, Vl, s_new + 1,
                                      attA, attM, attL, qs, sc, red, pvred);
            gbar(cnt);
            // out_part: (3, 48) = 144, len=16
            if (bid < 144) stage_part(bid % 3, bid / 3, nullptr, out_W + (size_t)l * D * D, part,
                                      D, D, 48, AP_ATT, nullptr, nullptr,
                                      attA, attM, attL, Asl, red, red2);
            gbar(cnt);
            // out_fin (+residual xv): 3, KS=48
            if (bid < 3) stage_fin(bid, part, out_b + l * D, xv, xv, D, 48, 0, 0, 0,
                                   nullptr, nullptr, nullptr);
            gbar(cnt);
            // ff1_part: (12, 12) = 144, len=64
            if (bid < 144) stage_part(bid % 12, bid / 12, xv, ff1_W + (size_t)l * D * DFF, part,
                                      DFF, D, 12, AP_LN, ln2_g + l * D, ln2_b + l * D,
                                      nullptr, nullptr, nullptr, Asl, red, red2);
            gbar(cnt);
            // ff1_fin (relu -> fv): 12, KS=12
            if (bid < 12) stage_fin(bid, part, ff1_b + l * DFF, nullptr, fv,
                                    DFF, 12, 1, 0, 0, nullptr, nullptr, nullptr);
            gbar(cnt);
            // ff2_part: (3, 48) = 144, len=64
            if (bid < 144) stage_part(bid % 3, bid / 3, fv, ff2_W + (size_t)l * DFF * D, part,
                                      D, DFF, 48, AP_PLAIN, nullptr, nullptr,
                                      nullptr, nullptr, nullptr, Asl, red, red2);
            gbar(cnt);
            // ff2_fin (+residual xv): 3, KS=48
            if (bid < 3) stage_fin(bid, part, ff2_b + l * D, xv, xv, D, 48, 0, 0, 0,
                                   nullptr, nullptr, nullptr);
            gbar(cnt);
        }
    }
}

// ------------------------- host orchestration -------------------------
extern "C" void kernel_launch(void* const* d_in, const int* in_sizes, int n_in,
                              void* d_out, int out_size) {
    const float* feats    = (const float*)d_in[0];
    const float* past     = (const float*)d_in[1];
    const int*   intent   = (const int*)  d_in[2];
    const float* img_pos  = (const float*)d_in[3];
    const float* time_emb = (const float*)d_in[4];
    const float* int_emb  = (const float*)d_in[5];
    const float* past_W   = (const float*)d_in[6];
    const float* past_b   = (const float*)d_in[7];
    const float* pos_W    = (const float*)d_in[8];
    const float* pos_b    = (const float*)d_in[9];
    const float* ln1_g    = (const float*)d_in[10];
    const float* ln1_b    = (const float*)d_in[11];
    const float* qkv_W    = (const float*)d_in[12];
    const float* qkv_b    = (const float*)d_in[13];
    const float* out_W    = (const float*)d_in[14];
    const float* out_b    = (const float*)d_in[15];
    const float* ln2_g    = (const float*)d_in[16];
    const float* ln2_b    = (const float*)d_in[17];
    const float* ff1_W    = (const float*)d_in[18];
    const float* ff1_b    = (const float*)d_in[19];
    const float* ff2_W    = (const float*)d_in[20];
    const float* ff2_b    = (const float*)d_in[21];
    const float* dec1_W   = (const float*)d_in[22];
    const float* dec1_b   = (const float*)d_in[23];
    const float* dec2_W   = (const float*)d_in[24];
    const float* dec2_b   = (const float*)d_in[25];
    float* out = (float*)d_out;

    float *px, *ph, *pqkv, *pff, *pctx, *pK, *pV, *pxv, *pqv, *pfv, *pgv;
    float *ppart, *pattA, *pattM, *pattL;
    cudaGetSymbolAddress((void**)&px,    g_x);
    cudaGetSymbolAddress((void**)&ph,    g_h);
    cudaGetSymbolAddress((void**)&pqkv,  g_qkv);
    cudaGetSymbolAddress((void**)&pff,   g_ff);
    cudaGetSymbolAddress((void**)&pctx,  g_ctx);
    cudaGetSymbolAddress((void**)&pK,    g_K);
    cudaGetSymbolAddress((void**)&pV,    g_V);
    cudaGetSymbolAddress((void**)&pxv,   g_xvec);
    cudaGetSymbolAddress((void**)&pqv,   g_qvec);
    cudaGetSymbolAddress((void**)&pfv,   g_fvec);
    cudaGetSymbolAddress((void**)&pgv,   g_gvec);
    cudaGetSymbolAddress((void**)&ppart, g_part);
    cudaGetSymbolAddress((void**)&pattA, g_attA);
    cudaGetSymbolAddress((void**)&pattM, g_attM);
    cudaGetSymbolAddress((void**)&pattL, g_attL);

    const int MB = (M0 + TM - 1) / TM;  // 17

    // ---- embed ----
    {
        int n = B * S0 * D;
        embed_kernel<<<(n + 255) / 256, 256>>>(feats, img_pos, intent, int_emb,
                                               past, past_W, past_b, time_emb, px);
    }

    // ---- prefill: 3 layers (tf32 tensor-core GEMMs, R12-proven) ----
    for (int l = 0; l < L; l++) {
        float* KcL = pK + (size_t)l * CACHE_L;
        float* VcL = pV + (size_t)l * CACHE_L;

        ln_kernel<<<M0, 256>>>(px, ph, ln1_g + l * D, ln1_b + l * D);
        gemm_kernel<<<dim3(D3 / TN, MB), 256>>>(
            ph, qkv_W + (size_t)l * D * D3, qkv_b + l * D3, nullptr, pqkv, M0, D3, D, 0);
        {
            int n = B * S0 * D;
            scatter_kv<<<(n + 255) / 256, 256>>>(pqkv, KcL, VcL);
        }
        attn_prefill<<<dim3((S0 + 3) / 4, B * H), 128>>>(pqkv, KcL, VcL, pctx);
        gemm_kernel<<<dim3(D / TN, MB), 256>>>(
            pctx, out_W + (size_t)l * D * D, out_b + l * D, px, px, M0, D, D, 0);
        ln_kernel<<<M0, 256>>>(px, ph, ln2_g + l * D, ln2_b + l * D);
        gemm_kernel<<<dim3(DFF / TN, MB), 256>>>(
            ph, ff1_W + (size_t)l * D * DFF, ff1_b + l * DFF, nullptr, pff, M0, DFF, D, 1);
        gemm_kernel<<<dim3(D / TN, MB), 256>>>(
            pff, ff2_W + (size_t)l * DFF * D, ff2_b + l * D, px, px, M0, D, DFF, 0);
    }

    copy_last<<<(B * D + 255) / 256, 256>>>(px, pxv);

    // ---- decode: persistent megakernel, 144-task part stages ----
    int nsm = 0;
    cudaDeviceGetAttribute(&nsm, cudaDevAttrMultiProcessorCount, 0);
    int nb = nsm < 148 ? nsm : 148;
    if (nb < 144) nb = 144;

    reset_bar_kernel<<<1, 1>>>();
    decode_mega<<<nb, 256>>>(
        qkv_W, qkv_b, out_W, out_b, ff1_W, ff1_b, ff2_W, ff2_b,
        ln1_g, ln1_b, ln2_g, ln2_b,
        dec1_W, dec1_b, dec2_W, dec2_b,
        pos_W, pos_b, time_emb,
        pxv, pqv, pfv, pgv, ppart,
        pK, pV, pattA, pattM, pattL, out);
}

// round 16
// speedup vs baseline: 1.1142x; 1.1142x over previous
#include <cuda_runtime.h>
#include <math.h>
#include <stdint.h>

#define B 2
#define D 768
#define H 16
#define HD 48
#define L 3
#define N_IMG 1024
#define N_PAST 16
#define T_DEC 20
#define S0 (N_IMG + 1 + N_PAST)    // 1041
#define SMAX (S0 + T_DEC)          // 1061
#define M0 (B * S0)                // 2082
#define D3 (3 * D)                 // 2304
#define DFF (4 * D)                // 3072
#define CACHE_L (B * H * SMAX * HD)
#define NSPLIT 4

#define ATT_SCALE 0.14433756729740643f  // 1/sqrt(48)

// ------------------------- static device scratch -------------------------
__device__ float g_x[M0 * D];
__device__ float g_h[M0 * D];
__device__ float g_qkv[M0 * D3];
__device__ float g_ff[M0 * DFF];
__device__ float g_ctx[M0 * D];
__device__ float g_K[L * CACHE_L];
__device__ float g_V[L * CACHE_L];
__device__ float g_xvec[B * D];
__device__ float g_qvec[B * D];
__device__ float g_fvec[B * DFF];
__device__ float g_gvec[B * D];
__device__ float g_part[16 * 2 * DFF];
__device__ float g_attA[B * H * NSPLIT * HD];
__device__ float g_attM[B * H * NSPLIT];
__device__ float g_attL[B * H * NSPLIT];
__device__ unsigned g_barcnt;

__device__ __forceinline__ float gelu_exact(float x) {
    return 0.5f * x * (1.0f + erff(x * 0.7071067811865475f));
}

__device__ __forceinline__ uint32_t f2tf32(float x) {
    uint32_t r;
    asm("cvt.rna.tf32.f32 %0, %1;" : "=r"(r) : "f"(x));
    return r;
}

__device__ __forceinline__ void mma_tf32(float* c, const uint32_t* a,
                                         uint32_t b0, uint32_t b1) {
    asm("mma.sync.aligned.m16n8k8.row.col.f32.tf32.tf32.f32 "
        "{%0,%1,%2,%3}, {%4,%5,%6,%7}, {%8,%9}, {%0,%1,%2,%3};"
        : "+f"(c[0]), "+f"(c[1]), "+f"(c[2]), "+f"(c[3])
        : "r"(a[0]), "r"(a[1]), "r"(a[2]), "r"(a[3]), "r"(b0), "r"(b1));
}

// ------------------------- embed -------------------------
__global__ void embed_kernel(const float* __restrict__ feats,
                             const float* __restrict__ img_pos,
                             const int* __restrict__ intent,
                             const float* __restrict__ int_emb,
                             const float* __restrict__ past,
                             const float* __restrict__ past_W,
                             const float* __restrict__ past_b,
                             const float* __restrict__ time_emb,
                             float* __restrict__ X) {
    int idx = blockIdx.x * blockDim.x + threadIdx.x;
    if (idx >= B * S0 * D) return;
    int d = idx % D;
    int s = (idx / D) % S0;
    int b = idx / (D * S0);
    float v;
    if (s < N_IMG) {
        v = feats[((size_t)b * D + d) * N_IMG + s] + img_pos[(size_t)s * D + d];
    } else if (s == N_IMG) {
        int ii = intent[b] - 1;
        ii = ii < 0 ? 0 : (ii > 2 ? 2 : ii);
        v = int_emb[ii * D + d];
    } else {
        int j = s - N_IMG - 1;
        v = past_b[d] + time_emb[j * D + d];
        #pragma unroll
        for (int c = 0; c < 6; c++)
            v += past[(b * N_PAST + j) * 6 + c] * past_W[c * D + d];
    }
    X[idx] = v;
}

// ------------------------- layernorm (prefill) -------------------------
__global__ void ln_kernel(const float* __restrict__ X, float* __restrict__ Y,
                          const float* __restrict__ gam, const float* __restrict__ bet) {
    int row = blockIdx.x;
    const float* x = X + (size_t)row * D;
    float* y = Y + (size_t)row * D;
    __shared__ float red[256];
    int t = threadIdx.x;
    float s = 0.f;
    for (int i = t; i < D; i += 256) s += x[i];
    red[t] = s; __syncthreads();
    for (int o = 128; o > 0; o >>= 1) { if (t < o) red[t] += red[t + o]; __syncthreads(); }
    float mean = red[0] * (1.0f / D);
    __syncthreads();
    float vs = 0.f;
    for (int i = t; i < D; i += 256) { float dd = x[i] - mean; vs += dd * dd; }
    red[t] = vs; __syncthreads();
    for (int o = 128; o > 0; o >>= 1) { if (t < o) red[t] += red[t + o]; __syncthreads(); }
    float inv = rsqrtf(red[0] * (1.0f / D) + 1e-5f);
    for (int i = t; i < D; i += 256)
        y[i] = (x[i] - mean) * inv * gam[i] + bet[i];
}

// ------------------------- tf32 tensor-core GEMM, DOUBLE BUFFERED -------------------------
#define TM 128
#define TN 128
#define TK 16
__global__ void __launch_bounds__(256)
gemm_kernel(const float* __restrict__ A, const float* __restrict__ W,
            const float* __restrict__ bias, const float* __restrict__ R,
            float* __restrict__ C, int M, int N, int K, int act) {
    __shared__ float As[2][TK][136];
    __shared__ float Ws[2][TK][136];
    int tid = threadIdx.x;
    int warp = tid >> 5, lane = tid & 31;
    int wm = warp & 1, wn = warp >> 1;
    int wrow = wm * 64, wcol = wn * 32;
    int row0 = blockIdx.y * TM, col0 = blockIdx.x * TN;
    int lq = lane >> 2, lr = lane & 3;

    float acc[4][4][4];
    #pragma unroll
    for (int i = 0; i < 4; i++)
        #pragma unroll
        for (int j = 0; j < 4; j++)
            #pragma unroll
            for (int r = 0; r < 4; r++) acc[i][j][r] = 0.f;

    const int nt = K / TK;

    // preload tile 0
    {
        #pragma unroll
        for (int i = 0; i < 2; i++) {
            int idx = tid * 2 + i;
            int r = idx >> 2, c4 = idx & 3;
            int gm = row0 + r;
            float4 v = make_float4(0.f, 0.f, 0.f, 0.f);
            if (gm < M) v = *reinterpret_cast<const float4*>(&A[(size_t)gm * K + c4 * 4]);
            As[0][c4 * 4 + 0][r] = v.x;
            As[0][c4 * 4 + 1][r] = v.y;
            As[0][c4 * 4 + 2][r] = v.z;
            As[0][c4 * 4 + 3][r] = v.w;
        }
        #pragma unroll
        for (int i = 0; i < 2; i++) {
            int idx = tid * 2 + i;
            int kk = idx >> 5, c4 = idx & 31;
            float4 v = *reinterpret_cast<const float4*>(&W[(size_t)kk * N + col0 + c4 * 4]);
            Ws[0][kk][c4 * 4 + 0] = v.x;
            Ws[0][kk][c4 * 4 + 1] = v.y;
            Ws[0][kk][c4 * 4 + 2] = v.z;
            Ws[0][kk][c4 * 4 + 3] = v.w;
        }
    }
    __syncthreads();

    for (int it = 0; it < nt; it++) {
        int buf = it & 1;
        int nxt = buf ^ 1;
        if (it + 1 < nt) {
            int k0 = (it + 1) * TK;
            #pragma unroll
            for (int i = 0; i < 2; i++) {
                int idx = tid * 2 + i;
                int r = idx >> 2, c4 = idx & 3;
                int gm = row0 + r;
                float4 v = make_float4(0.f, 0.f, 0.f, 0.f);
                if (gm < M) v = *reinterpret_cast<const float4*>(&A[(size_t)gm * K + k0 + c4 * 4]);
                As[nxt][c4 * 4 + 0][r] = v.x;
                As[nxt][c4 * 4 + 1][r] = v.y;
                As[nxt][c4 * 4 + 2][r] = v.z;
                As[nxt][c4 * 4 + 3][r] = v.w;
            }
            #pragma unroll
            for (int i = 0; i < 2; i++) {
                int idx = tid * 2 + i;
                int kk = idx >> 5, c4 = idx & 31;
                float4 v = *reinterpret_cast<const float4*>(&W[(size_t)(k0 + kk) * N + col0 + c4 * 4]);
                Ws[nxt][kk][c4 * 4 + 0] = v.x;
                Ws[nxt][kk][c4 * 4 + 1] = v.y;
                Ws[nxt][kk][c4 * 4 + 2] = v.z;
                Ws[nxt][kk][c4 * 4 + 3] = v.w;
            }
        }
        #pragma unroll
        for (int ks = 0; ks < 2; ks++) {
            int kb = ks * 8;
            uint32_t afr[4][4];
            #pragma unroll
            for (int ma = 0; ma < 4; ma++) {
                int r = wrow + ma * 16 + lq;
                int kk = kb + lr;
                afr[ma][0] = f2tf32(As[buf][kk][r]);
                afr[ma][1] = f2tf32(As[buf][kk][r + 8]);
                afr[ma][2] = f2tf32(As[buf][kk + 4][r]);
                afr[ma][3] = f2tf32(As[buf][kk + 4][r + 8]);
            }
            #pragma unroll
            for (int na = 0; na < 4; na++) {
                int n = wcol + na * 8 + lq;
                int kk = kb + lr;
                uint32_t b0 = f2tf32(Ws[buf][kk][n]);
                uint32_t b1 = f2tf32(Ws[buf][kk + 4][n]);
                #pragma unroll
                for (int ma = 0; ma < 4; ma++)
                    mma_tf32(acc[ma][na], afr[ma], b0, b1);
            }
        }
        __syncthreads();
    }

    #pragma unroll
    for (int ma = 0; ma < 4; ma++) {
        #pragma unroll
        for (int half = 0; half < 2; half++) {
            int gm = row0 + wrow + ma * 16 + lq + half * 8;
            if (gm >= M) continue;
            #pragma unroll
            for (int na = 0; na < 4; na++) {
                int gn = col0 + wcol + na * 8 + 2 * lr;
                float v0 = acc[ma][na][half * 2 + 0] + bias[gn];
                float v1 = acc[ma][na][half * 2 + 1] + bias[gn + 1];
                if (R) {
                    v0 += R[(size_t)gm * N + gn];
                    v1 += R[(size_t)gm * N + gn + 1];
                }
                if (act == 1) { v0 = fmaxf(v0, 0.f); v1 = fmaxf(v1, 0.f); }
                C[(size_t)gm * N + gn]     = v0;
                C[(size_t)gm * N + gn + 1] = v1;
            }
        }
    }
}

// ------------------------- scatter prefill K,V -------------------------
__global__ void scatter_kv(const float* __restrict__ qkv,
                           float* __restrict__ Kc, float* __restrict__ Vc) {
    int idx = blockIdx.x * blockDim.x + threadIdx.x;
    if (idx >= B * S0 * D) return;
    int e = idx % D;
    int s = (idx / D) % S0;
    int b = idx / (D * S0);
    int h = e / HD, ee = e % HD;
    size_t dst = (((size_t)(b * H + h)) * SMAX + s) * HD + ee;
    size_t src = ((size_t)(b * S0 + s)) * D3;
    Kc[dst] = qkv[src + D + e];
    Vc[dst] = qkv[src + 2 * D + e];
}

// ------------------------- prefill attention -------------------------
__global__ void attn_prefill(const float* __restrict__ QKV,
                             const float* __restrict__ Kc,
                             const float* __restrict__ Vc,
                             float* __restrict__ O) {
    int bh = blockIdx.y;
    int b = bh / H, h = bh % H;
    int q0 = blockIdx.x * 4;
    int warp = threadIdx.x >> 5, lane = threadIdx.x & 31;
    int qrow = q0 + warp;
    if (qrow >= S0) qrow = S0 - 1;

    __shared__ float qs[4][HD];
    __shared__ float Ks[32][49];
    __shared__ float Vs[32][49];

    {
        size_t qb = ((size_t)(b * S0 + qrow)) * D3 + h * HD;
        qs[warp][lane] = QKV[qb + lane];
        if (lane < 16) qs[warp][32 + lane] = QKV[qb + 32 + lane];
    }
    __syncthreads();

    int jmax_blk = q0 + 3; if (jmax_blk >= S0) jmax_blk = S0 - 1;
    size_t kvbase = (size_t)bh * SMAX * HD;

    float mrun = -INFINITY, srun = 0.f, acc0 = 0.f, acc1 = 0.f;

    for (int j0 = 0; j0 <= jmax_blk; j0 += 32) {
        for (int i = threadIdx.x; i < 32 * HD; i += 128) {
            int r = i / HD, c = i % HD;
            int j = j0 + r;
            float kv = 0.f, vv = 0.f;
            if (j < S0) {
                kv = Kc[kvbase + (size_t)j * HD + c];
                vv = Vc[kvbase + (size_t)j * HD + c];
            }
            Ks[r][c] = kv; Vs[r][c] = vv;
        }
        __syncthreads();

        int j = j0 + lane;
        float s = -INFINITY;
        if (j <= qrow) {
            s = 0.f;
            #pragma unroll
            for (int d = 0; d < HD; d++) s += qs[warp][d] * Ks[lane][d];
            s *= ATT_SCALE;
        }
        float cm = s;
        #pragma unroll
        for (int o = 16; o > 0; o >>= 1) cm = fmaxf(cm, __shfl_xor_sync(0xffffffffu, cm, o));
        float mnew = fmaxf(mrun, cm);
        float corr = expf(mrun - mnew);
        float p = (j <= qrow) ? expf(s - mnew) : 0.f;
        float ps = p;
        #pragma unroll
        for (int o = 16; o > 0; o >>= 1) ps += __shfl_xor_sync(0xffffffffu, ps, o);
        srun = srun * corr + ps;
        mrun = mnew;
        acc0 *= corr; acc1 *= corr;
        #pragma unroll 4
        for (int src = 0; src < 32; src++) {
            float pp = __shfl_sync(0xffffffffu, p, src);
            acc0 += pp * Vs[src][lane];
            if (lane < 16) acc1 += pp * Vs[src][32 + lane];
        }
        __syncthreads();
    }

    if (q0 + warp < S0) {
        float inv = 1.f / srun;
        size_t ob = ((size_t)(b * S0 + qrow)) * D + h * HD;
        O[ob + lane] = acc0 * inv;
        if (lane < 16) O[ob + 32 + lane] = acc1 * inv;
    }
}

__global__ void copy_last(const float* __restrict__ X, float* __restrict__ xv) {
    int idx = blockIdx.x * blockDim.x + threadIdx.x;
    if (idx >= B * D) return;
    int b = idx / D, d = idx % D;
    xv[idx] = X[((size_t)(b * S0 + S0 - 1)) * D + d];
}

__global__ void reset_bar_kernel() { g_barcnt = 0u; }

// ===================== decode MEGAKERNEL: R13 shapes + R11-proven folds =====================
#define AP_PLAIN 0
#define AP_LN    1
#define AP_ATT   2

__device__ __forceinline__ void gbar(int& cnt) {
    cnt++;
    __threadfence();
    __syncthreads();
    if (threadIdx.x == 0) {
        atomicAdd(&g_barcnt, 1u);
        unsigned target = (unsigned)cnt * gridDim.x;
        while (*(volatile unsigned*)&g_barcnt < target) { __nanosleep(64); }
    }
    __syncthreads();
    __threadfence();
}

__device__ void stage_part(int bx, int by,
                           const float* Avec, const float* W, float* part,
                           int N, int K, int KS, int mode,
                           const float* gam, const float* bet,
                           const float* attA, const float* attM, const float* attL,
                           float (*Asl)[192], float* red, float* red2) {
    int t = threadIdx.x;
    int len = K / KS;
    int k0 = by * len;

    if (mode == AP_PLAIN) {
        for (int i = t; i < 2 * len; i += 256) {
            int m = i / len, kk = i % len;
            Asl[m][kk] = __ldcg(Avec + m * K + k0 + kk);
        }
    } else if (mode == AP_LN) {
        float mean[2], inv[2];
        #pragma unroll
        for (int m = 0; m < 2; m++) {
            float s = 0.f, ss = 0.f;
            for (int i = t; i < K; i += 256) {
                float v = __ldcg(Avec + m * K + i);
                s += v; ss += v * v;
            }
            red[t] = s; red2[t] = ss; __syncthreads();
            for (int o = 128; o > 0; o >>= 1) {
                if (t < o) { red[t] += red[t + o]; red2[t] += red2[t + o]; }
                __syncthreads();
            }
            mean[m] = red[0] * (1.0f / D);
            inv[m] = rsqrtf(red2[0] * (1.0f / D) - mean[m] * mean[m] + 1e-5f);
            __syncthreads();
        }
        for (int i = t; i < 2 * len; i += 256) {
            int m = i / len, kk = i % len;
            int gk = k0 + kk;
            Asl[m][kk] = (__ldcg(Avec + m * K + gk) - mean[m]) * inv[m] * gam[gk] + bet[gk];
        }
    } else { // AP_ATT
        for (int i = t; i < 2 * len; i += 256) {
            int m = i / len, e = k0 + i % len;
            int h = e / HD, d = e % HD;
            int bh = m * H + h;
            float M = -INFINITY;
            #pragma unroll
            for (int s = 0; s < NSPLIT; s++) M = fmaxf(M, __ldcg(attM + bh * NSPLIT + s));
            float num = 0.f, den = 0.f;
            #pragma unroll
            for (int s = 0; s < NSPLIT; s++) {
                float w = expf(__ldcg(attM + bh * NSPLIT + s) - M);
                num += w * __ldcg(attA + (bh * NSPLIT + s) * HD + d);
                den += w * __ldcg(attL + bh * NSPLIT + s);
            }
            Asl[m][i % len] = num / den;
        }
    }
    __syncthreads();

    int n = bx * 256 + t;
    const float* Wp = W + (size_t)k0 * N + n;
    float a0 = 0.f, a1 = 0.f;
    #pragma unroll 8
    for (int kk = 0; kk < len; kk++) {
        float w = *Wp; Wp += N;
        a0 += Asl[0][kk] * w;
        a1 += Asl[1][kk] * w;
    }
    __stcg(part + (by * 2 + 0) * N + n, a0);
    __stcg(part + (by * 2 + 1) * N + n, a1);
}

__device__ void stage_fin(int bx, const float* part, const float* bias,
                          const float* Res, float* dst,
                          int N, int KS, int act) {
    int n = bx * 256 + threadIdx.x;
    float a0 = bias[n], a1 = a0;
    for (int ks = 0; ks < KS; ks++) {
        a0 += __ldcg(part + (ks * 2 + 0) * N + n);
        a1 += __ldcg(part + (ks * 2 + 1) * N + n);
    }
    if (Res) { a0 += __ldcg(Res + n); a1 += __ldcg(Res + N + n); }
    if (act == 1) { a0 = fmaxf(a0, 0.f); a1 = fmaxf(a1, 0.f); }
    __stcg(dst + n, a0); __stcg(dst + N + n, a1);
}

// attn with qkv_fin folded (R11-proven): q reduced per block; last split writes k/v_new
__device__ void stage_attn(int bh, int split,
                           const float* qkvPart, const float* qkv_bias,
                           float* Kc, float* Vc, int Slen,
                           float* attA, float* attM, float* attL,
                           float* qs, float* sc, float* red, float* pvred) {
    int b = bh / H, h = bh % H;
    int len = (Slen + NSPLIT - 1) / NSPLIT;
    int j0 = split * len;
    int j1 = min(j0 + len, Slen);
    int cnt = j1 - j0;
    int s_new = Slen - 1;
    int t = threadIdx.x;
    size_t base = (size_t)bh * SMAX * HD;

    if (t < HD) {
        int col = h * HD + t;
        float s = qkv_bias[col];
        #pragma unroll
        for (int ks = 0; ks < 8; ks++) s += __ldcg(qkvPart + (ks * 2 + b) * D3 + col);
        qs[t] = s;
    }
    if (split == NSPLIT - 1 && t >= 64 && t < 64 + 2 * HD) {
        int idx = t - 64;
        int which = idx / HD, ee = idx % HD;
        int col = D + which * D + h * HD + ee;
        float s = qkv_bias[col];
        #pragma unroll
        for (int ks = 0; ks < 8; ks++) s += __ldcg(qkvPart + (ks * 2 + b) * D3 + col);
        if (which == 0) __stcg(Kc + base + (size_t)s_new * HD + ee, s);
        else            __stcg(Vc + base + (size_t)s_new * HD + ee, s);
    }
    __syncthreads();

    float lmax = -INFINITY;
    for (int jl = t; jl < cnt; jl += 256) {
        const float* kp = Kc + base + (size_t)(j0 + jl) * HD;
        float s = 0.f;
        #pragma unroll
        for (int d = 0; d < HD; d++) s += qs[d] * __ldcg(kp + d);
        s *= ATT_SCALE;
        sc[jl] = s;
        lmax = fmaxf(lmax, s);
    }
    red[t] = lmax; __syncthreads();
    for (int o = 128; o > 0; o >>= 1) { if (t < o) red[t] = fmaxf(red[t], red[t + o]); __syncthreads(); }
    float m = red[0];
    __syncthreads();
    float ls = 0.f;
    for (int jl = t; jl < cnt; jl += 256) {
        float p = expf(sc[jl] - m);
        sc[jl] = p;
        ls += p;
    }
    red[t] = ls; __syncthreads();
    for (int o = 128; o > 0; o >>= 1) { if (t < o) red[t] += red[t + o]; __syncthreads(); }
    float l = red[0];
    __syncthreads();

    if (t < 5 * HD) {
        int d = t % HD, g = t / HD;
        float a = 0.f;
        for (int jl = g; jl < cnt; jl += 5)
            a += sc[jl] * __ldcg(Vc + base + (size_t)(j0 + jl) * HD + d);
        pvred[g * HD + d] = a;
    }
    __syncthreads();
    if (t < HD) {
        float a = pvred[t] + pvred[HD + t] + pvred[2 * HD + t] + pvred[3 * HD + t] + pvred[4 * HD + t];
        __stcg(attA + (bh * NSPLIT + split) * HD + t, a);
        if (t == 0) {
            __stcg(attM + bh * NSPLIT + split, m);
            __stcg(attL + bh * NSPLIT + split, l);
        }
    }
    __syncthreads();
}

// head2 with dec1_fin folded (R11-proven): reduces dec1 partials + gelu inline
__device__ void stage_head2(int b, const float* dec1Part, const float* dec1_b,
                            const float* dec2_W, const float* dec2_b,
                            const float* pos_W, const float* pos_b,
                            const float* time_emb, int t_step,
                            float* out, float* xv, float* r0, float* r1) {
    int tid = threadIdx.x;
    float p0 = 0.f, p1 = 0.f;
    for (int k = tid; k < D; k += 256) {
        float g = dec1_b[k];
        #pragma unroll
        for (int ks = 0; ks < 8; ks++) g += __ldcg(dec1Part + (ks * 2 + b) * D + k);
        g = gelu_exact(g);
        p0 += g * dec2_W[k * 2];
        p1 += g * dec2_W[k * 2 + 1];
    }
    r0[tid] = p0; r1[tid] = p1; __syncthreads();
    for (int o = 128; o > 0; o >>= 1) {
        if (tid < o) { r0[tid] += r0[tid + o]; r1[tid] += r1[tid + o]; }
        __syncthreads();
    }
    p0 = r0[0] + dec2_b[0];
    p1 = r1[0] + dec2_b[1];
    if (tid == 0) {
        __stcg(out + (b * T_DEC + t_step) * 2 + 0, p0);
        __stcg(out + (b * T_DEC + t_step) * 2 + 1, p1);
    }
    for (int d = tid; d < D; d += 256)
        __stcg(xv + b * D + d,
               p0 * pos_W[d] + p1 * pos_W[D + d] + pos_b[d]
               + time_emb[(N_PAST + t_step) * D + d]);
    __syncthreads();
}

__global__ void __launch_bounds__(256)
decode_mega(const float* __restrict__ qkv_W, const float* __restrict__ qkv_b,
            const float* __restrict__ out_W, const float* __restrict__ out_b,
            const float* __restrict__ ff1_W, const float* __restrict__ ff1_b,
            const float* __restrict__ ff2_W, const float* __restrict__ ff2_b,
            const float* __restrict__ ln1_g, const float* __restrict__ ln1_b,
            const float* __restrict__ ln2_g, const float* __restrict__ ln2_b,
            const float* __restrict__ dec1_W, const float* __restrict__ dec1_b,
            const float* __restrict__ dec2_W, const float* __restrict__ dec2_b,
            const float* __restrict__ pos_W, const float* __restrict__ pos_b,
            const float* __restrict__ time_emb,
            float* __restrict__ xv, float* __restrict__ fv,
            float* __restrict__ part,
            float* __restrict__ Kc, float* __restrict__ Vc,
            float* __restrict__ attA, float* __restrict__ attM,
            float* __restrict__ attL, float* __restrict__ out) {
    __shared__ float Asl[2][192];
    __shared__ float red[256], red2[256];
    __shared__ float sc[272], pvred[5 * HD], qs[64];

    int bid = blockIdx.x;
    int cnt = 0;

    for (int t = 0; t < T_DEC; t++) {
        // dec1_part: (3,8) = 24 tasks
        if (bid < 24) stage_part(bid % 3, bid / 3, xv, dec1_W, part, D, D, 8, AP_PLAIN,
                                 nullptr, nullptr, nullptr, nullptr, nullptr, Asl, red, red2);
        gbar(cnt);
        // head2 (dec1_fin folded): 2 tasks
        if (bid < 2) stage_head2(bid, part, dec1_b, dec2_W, dec2_b, pos_W, pos_b,
                                 time_emb, t, out, xv, red, red2);
        gbar(cnt);

        if (t == T_DEC - 1) break;
        int s_new = S0 + t;

        for (int l = 0; l < L; l++) {
            float* Kl = Kc + (size_t)l * CACHE_L;
            float* Vl = Vc + (size_t)l * CACHE_L;

            // qkv_part: (9,8) = 72
            if (bid < 72) stage_part(bid % 9, bid / 9, xv, qkv_W + (size_t)l * D * D3, part,
                                     D3, D, 8, AP_LN, ln1_g + l * D, ln1_b + l * D,
                                     nullptr, nullptr, nullptr, Asl, red, red2);
            gbar(cnt);
            // attn (qkv_fin folded): (32,4) = 128
            if (bid < 128) stage_attn(bid & 31, bid >> 5, part, qkv_b + l * D3,
                                      Kl, Vl, s_new + 1,
                                      attA, attM, attL, qs, sc, red, pvred);
            gbar(cnt);
            // out_part: (3,8) = 24
            if (bid < 24) stage_part(bid % 3, bid / 3, nullptr, out_W + (size_t)l * D * D, part,
                                     D, D, 8, AP_ATT, nullptr, nullptr,
                                     attA, attM, attL, Asl, red, red2);
            gbar(cnt);
            // out_fin (+residual xv): 3
            if (bid < 3) stage_fin(bid, part, out_b + l * D, xv, xv, D, 8, 0);
            gbar(cnt);
            // ff1_part: (12,8) = 96
            if (bid < 96) stage_part(bid % 12, bid / 12, xv, ff1_W + (size_t)l * D * DFF, part,
                                     DFF, D, 8, AP_LN, ln2_g + l * D, ln2_b + l * D,
                                     nullptr, nullptr, nullptr, Asl, red, red2);
            gbar(cnt);
            // ff1_fin (relu -> fv): 12
            if (bid < 12) stage_fin(bid, part, ff1_b + l * DFF, nullptr, fv, DFF, 8, 1);
            gbar(cnt);
            // ff2_part: (3,16) = 48
            if (bid < 48) stage_part(bid % 3, bid / 3, fv, ff2_W + (size_t)l * DFF * D, part,
                                     D, DFF, 16, AP_PLAIN, nullptr, nullptr,
                                     nullptr, nullptr, nullptr, Asl, red, red2);
            gbar(cnt);
            // ff2_fin (+residual xv): 3
            if (bid < 3) stage_fin(bid, part, ff2_b + l * D, xv, xv, D, 16, 0);
            gbar(cnt);
        }
    }
}

// ------------------------- host orchestration -------------------------
extern "C" void kernel_launch(void* const* d_in, const int* in_sizes, int n_in,
                              void* d_out, int out_size) {
    const float* feats    = (const float*)d_in[0];
    const float* past     = (const float*)d_in[1];
    const int*   intent   = (const int*)  d_in[2];
    const float* img_pos  = (const float*)d_in[3];
    const float* time_emb = (const float*)d_in[4];
    const float* int_emb  = (const float*)d_in[5];
    const float* past_W   = (const float*)d_in[6];
    const float* past_b   = (const float*)d_in[7];
    const float* pos_W    = (const float*)d_in[8];
    const float* pos_b    = (const float*)d_in[9];
    const float* ln1_g    = (const float*)d_in[10];
    const float* ln1_b    = (const float*)d_in[11];
    const float* qkv_W    = (const float*)d_in[12];
    const float* qkv_b    = (const float*)d_in[13];
    const float* out_W    = (const float*)d_in[14];
    const float* out_b    = (const float*)d_in[15];
    const float* ln2_g    = (const float*)d_in[16];
    const float* ln2_b    = (const float*)d_in[17];
    const float* ff1_W    = (const float*)d_in[18];
    const float* ff1_b    = (const float*)d_in[19];
    const float* ff2_W    = (const float*)d_in[20];
    const float* ff2_b    = (const float*)d_in[21];
    const float* dec1_W   = (const float*)d_in[22];
    const float* dec1_b   = (const float*)d_in[23];
    const float* dec2_W   = (const float*)d_in[24];
    const float* dec2_b   = (const float*)d_in[25];
    float* out = (float*)d_out;

    float *px, *ph, *pqkv, *pff, *pctx, *pK, *pV, *pxv, *pfv;
    float *ppart, *pattA, *pattM, *pattL;
    cudaGetSymbolAddress((void**)&px,    g_x);
    cudaGetSymbolAddress((void**)&ph,    g_h);
    cudaGetSymbolAddress((void**)&pqkv,  g_qkv);
    cudaGetSymbolAddress((void**)&pff,   g_ff);
    cudaGetSymbolAddress((void**)&pctx,  g_ctx);
    cudaGetSymbolAddress((void**)&pK,    g_K);
    cudaGetSymbolAddress((void**)&pV,    g_V);
    cudaGetSymbolAddress((void**)&pxv,   g_xvec);
    cudaGetSymbolAddress((void**)&pfv,   g_fvec);
    cudaGetSymbolAddress((void**)&ppart, g_part);
    cudaGetSymbolAddress((void**)&pattA, g_attA);
    cudaGetSymbolAddress((void**)&pattM, g_attM);
    cudaGetSymbolAddress((void**)&pattL, g_attL);

    const int MB = (M0 + TM - 1) / TM;  // 17

    // ---- embed ----
    {
        int n = B * S0 * D;
        embed_kernel<<<(n + 255) / 256, 256>>>(feats, img_pos, intent, int_emb,
                                               past, past_W, past_b, time_emb, px);
    }

    // ---- prefill: 3 layers (tf32 DB tensor-core GEMMs) ----
    for (int l = 0; l < L; l++) {
        float* KcL = pK + (size_t)l * CACHE_L;
        float* VcL = pV + (size_t)l * CACHE_L;

        ln_kernel<<<M0, 256>>>(px, ph, ln1_g + l * D, ln1_b + l * D);
        gemm_kernel<<<dim3(D3 / TN, MB), 256>>>(
            ph, qkv_W + (size_t)l * D * D3, qkv_b + l * D3, nullptr, pqkv, M0, D3, D, 0);
        {
            int n = B * S0 * D;
            scatter_kv<<<(n + 255) / 256, 256>>>(pqkv, KcL, VcL);
        }
        attn_prefill<<<dim3((S0 + 3) / 4, B * H), 128>>>(pqkv, KcL, VcL, pctx);
        gemm_kernel<<<dim3(D / TN, MB), 256>>>(
            pctx, out_W + (size_t)l * D * D, out_b + l * D, px, px, M0, D, D, 0);
        ln_kernel<<<M0, 256>>>(px, ph, ln2_g + l * D, ln2_b + l * D);
        gemm_kernel<<<dim3(DFF / TN, MB), 256>>>(
            ph, ff1_W + (size_t)l * D * DFF, ff1_b + l * DFF, nullptr, pff, M0, DFF, D, 1);
        gemm_kernel<<<dim3(D / TN, MB), 256>>>(
            pff, ff2_W + (size_t)l * DFF * D, ff2_b + l * D, px, px, M0, D, DFF, 0);
    }

    copy_last<<<(B * D + 255) / 256, 256>>>(px, pxv);

    // ---- decode: persistent megakernel (R13 shapes + folds) ----
    int nsm = 0;
    cudaDeviceGetAttribute(&nsm, cudaDevAttrMultiProcessorCount, 0);
    int nb = nsm < 148 ? nsm : 148;
    if (nb < 128) nb = 128;

    reset_bar_kernel<<<1, 1>>>();
    decode_mega<<<nb, 256>>>(
        qkv_W, qkv_b, out_W, out_b, ff1_W, ff1_b, ff2_W, ff2_b,
        ln1_g, ln1_b, ln2_g, ln2_b,
        dec1_W, dec1_b, dec2_W, dec2_b,
        pos_W, pos_b, time_emb,
        pxv, pfv, ppart,
        pK, pV, pattA, pattM, pattL, out);
}

// round 17
// speedup vs baseline: 1.3393x; 1.2021x over previous
#include <cuda_runtime.h>
#include <math.h>
#include <stdint.h>

#define B 2
#define D 768
#define H 16
#define HD 48
#define L 3
#define N_IMG 1024
#define N_PAST 16
#define T_DEC 20
#define S0 (N_IMG + 1 + N_PAST)    // 1041
#define SMAX (S0 + T_DEC)          // 1061
#define M0 (B * S0)                // 2082
#define D3 (3 * D)                 // 2304
#define DFF (4 * D)                // 3072
#define CACHE_L (B * H * SMAX * HD)
#define NSPLIT 4

#define ATT_SCALE 0.14433756729740643f  // 1/sqrt(48)

// src modes
#define SRC_VEC  0
#define SRC_FOLD 1
#define SRC_ATT  2
#define NORM_NONE 0
#define NORM_LN   1

// ------------------------- static device scratch -------------------------
__device__ float g_x[M0 * D];
__device__ float g_h[M0 * D];
__device__ float g_qkv[M0 * D3];
__device__ float g_ff[M0 * DFF];
__device__ float g_ctx[M0 * D];
__device__ float g_K[L * CACHE_L];
__device__ float g_V[L * CACHE_L];
__device__ float g_xvecA[B * D];
__device__ float g_xvecB[B * D];
// dedicated raw-partial buffers (no bias)
__device__ float g_Pdec1[8 * 2 * D];
__device__ float g_Pqkv[8 * 2 * D3];
__device__ float g_Pout[8 * 2 * D];
__device__ float g_Pff1[8 * 2 * DFF];
__device__ float g_Pff2[16 * 2 * D];
__device__ float g_attA[B * H * NSPLIT * HD];
__device__ float g_attM[B * H * NSPLIT];
__device__ float g_attL[B * H * NSPLIT];
__device__ unsigned g_barcnt;

__device__ __forceinline__ float gelu_exact(float x) {
    return 0.5f * x * (1.0f + erff(x * 0.7071067811865475f));
}

__device__ __forceinline__ uint32_t f2tf32(float x) {
    uint32_t r;
    asm("cvt.rna.tf32.f32 %0, %1;" : "=r"(r) : "f"(x));
    return r;
}

__device__ __forceinline__ void mma_tf32(float* c, const uint32_t* a,
                                         uint32_t b0, uint32_t b1) {
    asm("mma.sync.aligned.m16n8k8.row.col.f32.tf32.tf32.f32 "
        "{%0,%1,%2,%3}, {%4,%5,%6,%7}, {%8,%9}, {%0,%1,%2,%3};"
        : "+f"(c[0]), "+f"(c[1]), "+f"(c[2]), "+f"(c[3])
        : "r"(a[0]), "r"(a[1]), "r"(a[2]), "r"(a[3]), "r"(b0), "r"(b1));
}

// ------------------------- embed -------------------------
__global__ void embed_kernel(const float* __restrict__ feats,
                             const float* __restrict__ img_pos,
                             const int* __restrict__ intent,
                             const float* __restrict__ int_emb,
                             const float* __restrict__ past,
                             const float* __restrict__ past_W,
                             const float* __restrict__ past_b,
                             const float* __restrict__ time_emb,
                             float* __restrict__ X) {
    int idx = blockIdx.x * blockDim.x + threadIdx.x;
    if (idx >= B * S0 * D) return;
    int d = idx % D;
    int s = (idx / D) % S0;
    int b = idx / (D * S0);
    float v;
    if (s < N_IMG) {
        v = feats[((size_t)b * D + d) * N_IMG + s] + img_pos[(size_t)s * D + d];
    } else if (s == N_IMG) {
        int ii = intent[b] - 1;
        ii = ii < 0 ? 0 : (ii > 2 ? 2 : ii);
        v = int_emb[ii * D + d];
    } else {
        int j = s - N_IMG - 1;
        v = past_b[d] + time_emb[j * D + d];
        #pragma unroll
        for (int c = 0; c < 6; c++)
            v += past[(b * N_PAST + j) * 6 + c] * past_W[c * D + d];
    }
    X[idx] = v;
}

// ------------------------- layernorm (prefill) -------------------------
__global__ void ln_kernel(const float* __restrict__ X, float* __restrict__ Y,
                          const float* __restrict__ gam, const float* __restrict__ bet) {
    int row = blockIdx.x;
    const float* x = X + (size_t)row * D;
    float* y = Y + (size_t)row * D;
    __shared__ float red[256];
    int t = threadIdx.x;
    float s = 0.f;
    for (int i = t; i < D; i += 256) s += x[i];
    red[t] = s; __syncthreads();
    for (int o = 128; o > 0; o >>= 1) { if (t < o) red[t] += red[t + o]; __syncthreads(); }
    float mean = red[0] * (1.0f / D);
    __syncthreads();
    float vs = 0.f;
    for (int i = t; i < D; i += 256) { float dd = x[i] - mean; vs += dd * dd; }
    red[t] = vs; __syncthreads();
    for (int o = 128; o > 0; o >>= 1) { if (t < o) red[t] += red[t + o]; __syncthreads(); }
    float inv = rsqrtf(red[0] * (1.0f / D) + 1e-5f);
    for (int i = t; i < D; i += 256)
        y[i] = (x[i] - mean) * inv * gam[i] + bet[i];
}

// ------------------------- tf32 tensor-core GEMM, double buffered (R15-proven) -------------------------
#define TM 128
#define TN 128
#define TK 16
__global__ void __launch_bounds__(256)
gemm_kernel(const float* __restrict__ A, const float* __restrict__ W,
            const float* __restrict__ bias, const float* __restrict__ R,
            float* __restrict__ C, int M, int N, int K, int act) {
    __shared__ float As[2][TK][136];
    __shared__ float Ws[2][TK][136];
    int tid = threadIdx.x;
    int warp = tid >> 5, lane = tid & 31;
    int wm = warp & 1, wn = warp >> 1;
    int wrow = wm * 64, wcol = wn * 32;
    int row0 = blockIdx.y * TM, col0 = blockIdx.x * TN;
    int lq = lane >> 2, lr = lane & 3;

    float acc[4][4][4];
    #pragma unroll
    for (int i = 0; i < 4; i++)
        #pragma unroll
        for (int j = 0; j < 4; j++)
            #pragma unroll
            for (int r = 0; r < 4; r++) acc[i][j][r] = 0.f;

    const int nt = K / TK;

    {
        #pragma unroll
        for (int i = 0; i < 2; i++) {
            int idx = tid * 2 + i;
            int r = idx >> 2, c4 = idx & 3;
            int gm = row0 + r;
            float4 v = make_float4(0.f, 0.f, 0.f, 0.f);
            if (gm < M) v = *reinterpret_cast<const float4*>(&A[(size_t)gm * K + c4 * 4]);
            As[0][c4 * 4 + 0][r] = v.x;
            As[0][c4 * 4 + 1][r] = v.y;
            As[0][c4 * 4 + 2][r] = v.z;
            As[0][c4 * 4 + 3][r] = v.w;
        }
        #pragma unroll
        for (int i = 0; i < 2; i++) {
            int idx = tid * 2 + i;
            int kk = idx >> 5, c4 = idx & 31;
            float4 v = *reinterpret_cast<const float4*>(&W[(size_t)kk * N + col0 + c4 * 4]);
            Ws[0][kk][c4 * 4 + 0] = v.x;
            Ws[0][kk][c4 * 4 + 1] = v.y;
            Ws[0][kk][c4 * 4 + 2] = v.z;
            Ws[0][kk][c4 * 4 + 3] = v.w;
        }
    }
    __syncthreads();

    for (int it = 0; it < nt; it++) {
        int buf = it & 1;
        int nxt = buf ^ 1;
        if (it + 1 < nt) {
            int k0 = (it + 1) * TK;
            #pragma unroll
            for (int i = 0; i < 2; i++) {
                int idx = tid * 2 + i;
                int r = idx >> 2, c4 = idx & 3;
                int gm = row0 + r;
                float4 v = make_float4(0.f, 0.f, 0.f, 0.f);
                if (gm < M) v = *reinterpret_cast<const float4*>(&A[(size_t)gm * K + k0 + c4 * 4]);
                As[nxt][c4 * 4 + 0][r] = v.x;
                As[nxt][c4 * 4 + 1][r] = v.y;
                As[nxt][c4 * 4 + 2][r] = v.z;
                As[nxt][c4 * 4 + 3][r] = v.w;
            }
            #pragma unroll
            for (int i = 0; i < 2; i++) {
                int idx = tid * 2 + i;
                int kk = idx >> 5, c4 = idx & 31;
                float4 v = *reinterpret_cast<const float4*>(&W[(size_t)(k0 + kk) * N + col0 + c4 * 4]);
                Ws[nxt][kk][c4 * 4 + 0] = v.x;
                Ws[nxt][kk][c4 * 4 + 1] = v.y;
                Ws[nxt][kk][c4 * 4 + 2] = v.z;
                Ws[nxt][kk][c4 * 4 + 3] = v.w;
            }
        }
        #pragma unroll
        for (int ks = 0; ks < 2; ks++) {
            int kb = ks * 8;
            uint32_t afr[4][4];
            #pragma unroll
            for (int ma = 0; ma < 4; ma++) {
                int r = wrow + ma * 16 + lq;
                int kk = kb + lr;
                afr[ma][0] = f2tf32(As[buf][kk][r]);
                afr[ma][1] = f2tf32(As[buf][kk][r + 8]);
                afr[ma][2] = f2tf32(As[buf][kk + 4][r]);
                afr[ma][3] = f2tf32(As[buf][kk + 4][r + 8]);
            }
            #pragma unroll
            for (int na = 0; na < 4; na++) {
                int n = wcol + na * 8 + lq;
                int kk = kb + lr;
                uint32_t b0 = f2tf32(Ws[buf][kk][n]);
                uint32_t b1 = f2tf32(Ws[buf][kk + 4][n]);
                #pragma unroll
                for (int ma = 0; ma < 4; ma++)
                    mma_tf32(acc[ma][na], afr[ma], b0, b1);
            }
        }
        __syncthreads();
    }

    #pragma unroll
    for (int ma = 0; ma < 4; ma++) {
        #pragma unroll
        for (int half = 0; half < 2; half++) {
            int gm = row0 + wrow + ma * 16 + lq + half * 8;
            if (gm >= M) continue;
            #pragma unroll
            for (int na = 0; na < 4; na++) {
                int gn = col0 + wcol + na * 8 + 2 * lr;
                float v0 = acc[ma][na][half * 2 + 0] + bias[gn];
                float v1 = acc[ma][na][half * 2 + 1] + bias[gn + 1];
                if (R) {
                    v0 += R[(size_t)gm * N + gn];
                    v1 += R[(size_t)gm * N + gn + 1];
                }
                if (act == 1) { v0 = fmaxf(v0, 0.f); v1 = fmaxf(v1, 0.f); }
                C[(size_t)gm * N + gn]     = v0;
                C[(size_t)gm * N + gn + 1] = v1;
            }
        }
    }
}

// ------------------------- scatter prefill K,V -------------------------
__global__ void scatter_kv(const float* __restrict__ qkv,
                           float* __restrict__ Kc, float* __restrict__ Vc) {
    int idx = blockIdx.x * blockDim.x + threadIdx.x;
    if (idx >= B * S0 * D) return;
    int e = idx % D;
    int s = (idx / D) % S0;
    int b = idx / (D * S0);
    int h = e / HD, ee = e % HD;
    size_t dst = (((size_t)(b * H + h)) * SMAX + s) * HD + ee;
    size_t src = ((size_t)(b * S0 + s)) * D3;
    Kc[dst] = qkv[src + D + e];
    Vc[dst] = qkv[src + 2 * D + e];
}

// ------------------------- prefill attention -------------------------
__global__ void attn_prefill(const float* __restrict__ QKV,
                             const float* __restrict__ Kc,
                             const float* __restrict__ Vc,
                             float* __restrict__ O) {
    int bh = blockIdx.y;
    int b = bh / H, h = bh % H;
    int q0 = blockIdx.x * 4;
    int warp = threadIdx.x >> 5, lane = threadIdx.x & 31;
    int qrow = q0 + warp;
    if (qrow >= S0) qrow = S0 - 1;

    __shared__ float qs[4][HD];
    __shared__ float Ks[32][49];
    __shared__ float Vs[32][49];

    {
        size_t qb = ((size_t)(b * S0 + qrow)) * D3 + h * HD;
        qs[warp][lane] = QKV[qb + lane];
        if (lane < 16) qs[warp][32 + lane] = QKV[qb + 32 + lane];
    }
    __syncthreads();

    int jmax_blk = q0 + 3; if (jmax_blk >= S0) jmax_blk = S0 - 1;
    size_t kvbase = (size_t)bh * SMAX * HD;

    float mrun = -INFINITY, srun = 0.f, acc0 = 0.f, acc1 = 0.f;

    for (int j0 = 0; j0 <= jmax_blk; j0 += 32) {
        for (int i = threadIdx.x; i < 32 * HD; i += 128) {
            int r = i / HD, c = i % HD;
            int j = j0 + r;
            float kv = 0.f, vv = 0.f;
            if (j < S0) {
                kv = Kc[kvbase + (size_t)j * HD + c];
                vv = Vc[kvbase + (size_t)j * HD + c];
            }
            Ks[r][c] = kv; Vs[r][c] = vv;
        }
        __syncthreads();

        int j = j0 + lane;
        float s = -INFINITY;
        if (j <= qrow) {
            s = 0.f;
            #pragma unroll
            for (int d = 0; d < HD; d++) s += qs[warp][d] * Ks[lane][d];
            s *= ATT_SCALE;
        }
        float cm = s;
        #pragma unroll
        for (int o = 16; o > 0; o >>= 1) cm = fmaxf(cm, __shfl_xor_sync(0xffffffffu, cm, o));
        float mnew = fmaxf(mrun, cm);
        float corr = expf(mrun - mnew);
        float p = (j <= qrow) ? expf(s - mnew) : 0.f;
        float ps = p;
        #pragma unroll
        for (int o = 16; o > 0; o >>= 1) ps += __shfl_xor_sync(0xffffffffu, ps, o);
        srun = srun * corr + ps;
        mrun = mnew;
        acc0 *= corr; acc1 *= corr;
        #pragma unroll 4
        for (int src = 0; src < 32; src++) {
            float pp = __shfl_sync(0xffffffffu, p, src);
            acc0 += pp * Vs[src][lane];
            if (lane < 16) acc1 += pp * Vs[src][32 + lane];
        }
        __syncthreads();
    }

    if (q0 + warp < S0) {
        float inv = 1.f / srun;
        size_t ob = ((size_t)(b * S0 + qrow)) * D + h * HD;
        O[ob + lane] = acc0 * inv;
        if (lane < 16) O[ob + 32 + lane] = acc1 * inv;
    }
}

__global__ void copy_last(const float* __restrict__ X, float* __restrict__ xv) {
    int idx = blockIdx.x * blockDim.x + threadIdx.x;
    if (idx >= B * D) return;
    int b = idx / D, d = idx % D;
    xv[idx] = X[((size_t)(b * S0 + S0 - 1)) * D + d];
}

__global__ void reset_bar_kernel() { g_barcnt = 0u; }

// ===================== decode MEGAKERNEL: full R11 folds, 17 stages/step =====================
__device__ __forceinline__ void gbar(int& cnt) {
    cnt++;
    __threadfence();
    __syncthreads();
    if (threadIdx.x == 0) {
        atomicAdd(&g_barcnt, 1u);
        unsigned target = (unsigned)cnt * gridDim.x;
        while (*(volatile unsigned*)&g_barcnt < target) { __nanosleep(64); }
    }
    __syncthreads();
    __threadfence();
}

// part stage with fold-capable prologue (R11-proven logic, ldcg/stcg discipline)
__device__ void stage_partF(int bx, int by,
                            const float* vec, const float* xvRes,
                            const float* prevPart, const float* prevBias,
                            int prevKS, int prevN, int foldFull, int foldRelu,
                            float* xvWB,
                            const float* W, float* part,
                            int N, int K, int KS, int norm,
                            const float* gam, const float* bet,
                            const float* attA, const float* attM,
                            const float* attL, int srcMode,
                            float (*xs)[D], float (*Asl)[192], float* red) {
    int t = threadIdx.x, lane = t & 31, w = t >> 5;
    int len = K / KS;
    int k0 = by * len;

    if (srcMode == SRC_ATT) {
        for (int i = t; i < 2 * len; i += 256) {
            int m = i / len, e = k0 + i % len;
            int h = e / HD, d = e % HD;
            int bh = m * H + h;
            float M = -INFINITY;
            #pragma unroll
            for (int s = 0; s < NSPLIT; s++) M = fmaxf(M, __ldcg(attM + bh * NSPLIT + s));
            float num = 0.f, den = 0.f;
            #pragma unroll
            for (int s = 0; s < NSPLIT; s++) {
                float wexp = expf(__ldcg(attM + bh * NSPLIT + s) - M);
                num += wexp * __ldcg(attA + (bh * NSPLIT + s) * HD + d);
                den += wexp * __ldcg(attL + bh * NSPLIT + s);
            }
            Asl[m][i % len] = num / den;
        }
    } else if (srcMode == SRC_VEC && norm == NORM_NONE) {
        for (int i = t; i < 2 * len; i += 256) {
            int m = i / len, kk = i % len;
            Asl[m][kk] = __ldcg(vec + m * K + k0 + kk);
        }
    } else if (srcMode == SRC_FOLD && !foldFull) {
        // slice-only fold (+optional relu +optional residual)
        for (int i = t; i < 2 * len; i += 256) {
            int m = i / len, kk = i % len;
            int gk = k0 + kk;
            float v = prevBias[gk];
            if (xvRes) v += __ldcg(xvRes + m * K + gk);
            for (int ks = 0; ks < prevKS; ks++)
                v += __ldcg(prevPart + (ks * 2 + m) * prevN + gk);
            if (foldRelu) v = fmaxf(v, 0.f);
            Asl[m][kk] = v;
        }
    } else {
        // full activation into xs (K == D on these paths)
        if (srcMode == SRC_VEC) {
            for (int i = t; i < 2 * D; i += 256) {
                int m = i / D, d = i % D;
                xs[m][d] = __ldcg(vec + m * D + d);
            }
        } else {
            for (int i = t; i < 2 * D; i += 256) {
                int m = i / D, d = i % D;
                float v = prevBias[d];
                if (xvRes) v += __ldcg(xvRes + m * D + d);
                for (int ks = 0; ks < prevKS; ks++)
                    v += __ldcg(prevPart + (ks * 2 + m) * prevN + d);
                xs[m][d] = v;
            }
        }
        __syncthreads();
        if (xvWB && bx == 0 && by == 0) {
            for (int i = t; i < 2 * D; i += 256) {
                int m = i / D, d = i % D;
                __stcg(xvWB + m * D + d, xs[m][d]);
            }
        }
        if (norm == NORM_LN) {
            // fast single-sweep warp-reduced stats (R10-proven pattern)
            float sA = 0.f, qA = 0.f, sB = 0.f, qB = 0.f;
            for (int i = t; i < D; i += 256) {
                float v0 = xs[0][i], v1 = xs[1][i];
                sA += v0; qA += v0 * v0;
                sB += v1; qB += v1 * v1;
            }
            #pragma unroll
            for (int o = 16; o > 0; o >>= 1) {
                sA += __shfl_xor_sync(0xffffffffu, sA, o);
                qA += __shfl_xor_sync(0xffffffffu, qA, o);
                sB += __shfl_xor_sync(0xffffffffu, sB, o);
                qB += __shfl_xor_sync(0xffffffffu, qB, o);
            }
            if (lane == 0) { red[w] = sA; red[8 + w] = qA; red[16 + w] = sB; red[24 + w] = qB; }
            __syncthreads();
            if (t == 0) {
                float SA = 0.f, QA = 0.f, SB = 0.f, QB = 0.f;
                #pragma unroll
                for (int i = 0; i < 8; i++) {
                    SA += red[i]; QA += red[8 + i]; SB += red[16 + i]; QB += red[24 + i];
                }
                float m0 = SA * (1.0f / D), m1 = SB * (1.0f / D);
                red[32] = m0; red[33] = rsqrtf(QA * (1.0f / D) - m0 * m0 + 1e-5f);
                red[34] = m1; red[35] = rsqrtf(QB * (1.0f / D) - m1 * m1 + 1e-5f);
            }
            __syncthreads();
            float m0 = red[32], r0 = red[33], m1 = red[34], r1 = red[35];
            for (int i = t; i < 2 * len; i += 256) {
                int m = i / len, kk = i % len;
                int gk = k0 + kk;
                float mm = (m == 0) ? m0 : m1;
                float rr = (m == 0) ? r0 : r1;
                Asl[m][kk] = (xs[m][gk] - mm) * rr * gam[gk] + bet[gk];
            }
        } else {
            for (int i = t; i < 2 * len; i += 256) {
                int m = i / len, kk = i % len;
                Asl[m][kk] = xs[m][k0 + kk];
            }
        }
    }
    __syncthreads();

    int n = bx * 256 + t;
    const float* Wp = W + (size_t)k0 * N + n;
    float a0 = 0.f, a1 = 0.f;
    #pragma unroll 16
    for (int kk = 0; kk < len; kk++) {
        float ww = *Wp; Wp += N;
        a0 += Asl[0][kk] * ww;
        a1 += Asl[1][kk] * ww;
    }
    __stcg(part + (by * 2 + 0) * N + n, a0);
    __stcg(part + (by * 2 + 1) * N + n, a1);
}

// attn with qkv_fin folded (R15-proven)
__device__ void stage_attn(int bh, int split,
                           const float* qkvPart, const float* qkv_bias,
                           float* Kc, float* Vc, int Slen,
                           float* attA, float* attM, float* attL,
                           float* qs, float* sc, float* red, float* pvred) {
    int b = bh / H, h = bh % H;
    int len = (Slen + NSPLIT - 1) / NSPLIT;
    int j0 = split * len;
    int j1 = min(j0 + len, Slen);
    int cnt = j1 - j0;
    int s_new = Slen - 1;
    int t = threadIdx.x;
    size_t base = (size_t)bh * SMAX * HD;

    if (t < HD) {
        int col = h * HD + t;
        float s = qkv_bias[col];
        #pragma unroll
        for (int ks = 0; ks < 8; ks++) s += __ldcg(qkvPart + (ks * 2 + b) * D3 + col);
        qs[t] = s;
    }
    if (split == NSPLIT - 1 && t >= 64 && t < 64 + 2 * HD) {
        int idx = t - 64;
        int which = idx / HD, ee = idx % HD;
        int col = D + which * D + h * HD + ee;
        float s = qkv_bias[col];
        #pragma unroll
        for (int ks = 0; ks < 8; ks++) s += __ldcg(qkvPart + (ks * 2 + b) * D3 + col);
        if (which == 0) __stcg(Kc + base + (size_t)s_new * HD + ee, s);
        else            __stcg(Vc + base + (size_t)s_new * HD + ee, s);
    }
    __syncthreads();

    float lmax = -INFINITY;
    for (int jl = t; jl < cnt; jl += 256) {
        const float* kp = Kc + base + (size_t)(j0 + jl) * HD;
        float s = 0.f;
        #pragma unroll
        for (int d = 0; d < HD; d++) s += qs[d] * __ldcg(kp + d);
        s *= ATT_SCALE;
        sc[jl] = s;
        lmax = fmaxf(lmax, s);
    }
    red[t] = lmax; __syncthreads();
    for (int o = 128; o > 0; o >>= 1) { if (t < o) red[t] = fmaxf(red[t], red[t + o]); __syncthreads(); }
    float m = red[0];
    __syncthreads();
    float ls = 0.f;
    for (int jl = t; jl < cnt; jl += 256) {
        float p = expf(sc[jl] - m);
        sc[jl] = p;
        ls += p;
    }
    red[t] = ls; __syncthreads();
    for (int o = 128; o > 0; o >>= 1) { if (t < o) red[t] += red[t + o]; __syncthreads(); }
    float l = red[0];
    __syncthreads();

    if (t < 5 * HD) {
        int d = t % HD, g = t / HD;
        float a = 0.f;
        for (int jl = g; jl < cnt; jl += 5)
            a += sc[jl] * __ldcg(Vc + base + (size_t)(j0 + jl) * HD + d);
        pvred[g * HD + d] = a;
    }
    __syncthreads();
    if (t < HD) {
        float a = pvred[t] + pvred[HD + t] + pvred[2 * HD + t] + pvred[3 * HD + t] + pvred[4 * HD + t];
        __stcg(attA + (bh * NSPLIT + split) * HD + t, a);
        if (t == 0) {
            __stcg(attM + bh * NSPLIT + split, m);
            __stcg(attL + bh * NSPLIT + split, l);
        }
    }
    __syncthreads();
}

// head2 with dec1_fin folded (R15-proven)
__device__ void stage_head2(int b, const float* dec1Part, const float* dec1_b,
                            const float* dec2_W, const float* dec2_b,
                            const float* pos_W, const float* pos_b,
                            const float* time_emb, int t_step,
                            float* out, float* xv, float* r0, float* r1) {
    int tid = threadIdx.x;
    float p0 = 0.f, p1 = 0.f;
    for (int k = tid; k < D; k += 256) {
        float g = dec1_b[k];
        #pragma unroll
        for (int ks = 0; ks < 8; ks++) g += __ldcg(dec1Part + (ks * 2 + b) * D + k);
        g = gelu_exact(g);
        p0 += g * dec2_W[k * 2];
        p1 += g * dec2_W[k * 2 + 1];
    }
    r0[tid] = p0; r1[tid] = p1; __syncthreads();
    for (int o = 128; o > 0; o >>= 1) {
        if (tid < o) { r0[tid] += r0[tid + o]; r1[tid] += r1[tid + o]; }
        __syncthreads();
    }
    p0 = r0[0] + dec2_b[0];
    p1 = r1[0] + dec2_b[1];
    if (tid == 0) {
        __stcg(out + (b * T_DEC + t_step) * 2 + 0, p0);
        __stcg(out + (b * T_DEC + t_step) * 2 + 1, p1);
    }
    for (int d = tid; d < D; d += 256)
        __stcg(xv + b * D + d,
               p0 * pos_W[d] + p1 * pos_W[D + d] + pos_b[d]
               + time_emb[(N_PAST + t_step) * D + d]);
    __syncthreads();
}

__global__ void __launch_bounds__(256)
decode_mega(const float* __restrict__ qkv_W, const float* __restrict__ qkv_b,
            const float* __restrict__ out_W, const float* __restrict__ out_b,
            const float* __restrict__ ff1_W, const float* __restrict__ ff1_b,
            const float* __restrict__ ff2_W, const float* __restrict__ ff2_b,
            const float* __restrict__ ln1_g, const float* __restrict__ ln1_b,
            const float* __restrict__ ln2_g, const float* __restrict__ ln2_b,
            const float* __restrict__ dec1_W, const float* __restrict__ dec1_b,
            const float* __restrict__ dec2_W, const float* __restrict__ dec2_b,
            const float* __restrict__ pos_W, const float* __restrict__ pos_b,
            const float* __restrict__ time_emb,
            float* __restrict__ xvA, float* __restrict__ xvB,
            float* __restrict__ Pdec1, float* __restrict__ Pqkv,
            float* __restrict__ Pout, float* __restrict__ Pff1,
            float* __restrict__ Pff2,
            float* __restrict__ Kc, float* __restrict__ Vc,
            float* __restrict__ attA, float* __restrict__ attM,
            float* __restrict__ attL, float* __restrict__ out) {
    __shared__ float xs[2][D];
    __shared__ float Asl[2][192];
    __shared__ float red[256], red2[256];
    __shared__ float sc[272], pvred[5 * HD], qs[64];

    int bid = blockIdx.x;
    int cnt = 0;

    for (int t = 0; t < T_DEC; t++) {
        // dec1_part: 24 tasks. t=0: plain from xvA; t>0: slice-fold ff2(l2)+xvB
        if (bid < 24) {
            if (t == 0)
                stage_partF(bid % 3, bid / 3, xvA, nullptr,
                            nullptr, nullptr, 0, 0, 0, 0, nullptr,
                            dec1_W, Pdec1, D, D, 8, NORM_NONE,
                            nullptr, nullptr, nullptr, nullptr, nullptr, SRC_VEC,
                            xs, Asl, red);
            else
                stage_partF(bid % 3, bid / 3, nullptr, xvB,
                            Pff2, ff2_b + 2 * D, 16, D, 0, 0, nullptr,
                            dec1_W, Pdec1, D, D, 8, NORM_NONE,
                            nullptr, nullptr, nullptr, nullptr, nullptr, SRC_FOLD,
                            xs, Asl, red);
        }
        gbar(cnt);
        // head2 (dec1_fin folded): 2 tasks -> out, xvA(new token)
        if (bid < 2) stage_head2(bid, Pdec1, dec1_b, dec2_W, dec2_b, pos_W, pos_b,
                                 time_emb, t, out, xvA, red, red2);
        gbar(cnt);

        if (t == T_DEC - 1) break;
        int s_new = S0 + t;

        for (int l = 0; l < L; l++) {
            float* Kl = Kc + (size_t)l * CACHE_L;
            float* Vl = Vc + (size_t)l * CACHE_L;

            // qkv_part: 72 tasks, LN1. l=0: from xvA; l>=1: full-fold ff2(l-1)+xvB -> WB xvA
            if (bid < 72) {
                if (l == 0)
                    stage_partF(bid % 9, bid / 9, xvA, nullptr,
                                nullptr, nullptr, 0, 0, 1, 0, nullptr,
                                qkv_W + (size_t)l * D * D3, Pqkv, D3, D, 8, NORM_LN,
                                ln1_g + l * D, ln1_b + l * D,
                                nullptr, nullptr, nullptr, SRC_VEC,
                                xs, Asl, red);
                else
                    stage_partF(bid % 9, bid / 9, nullptr, xvB,
                                Pff2, ff2_b + (l - 1) * D, 16, D, 1, 0, xvA,
                                qkv_W + (size_t)l * D * D3, Pqkv, D3, D, 8, NORM_LN,
                                ln1_g + l * D, ln1_b + l * D,
                                nullptr, nullptr, nullptr, SRC_FOLD,
                                xs, Asl, red);
            }
            gbar(cnt);
            // attn (qkv_fin folded): 128 tasks
            if (bid < 128) stage_attn(bid & 31, bid >> 5, Pqkv, qkv_b + l * D3,
                                      Kl, Vl, s_new + 1,
                                      attA, attM, attL, qs, sc, red, pvred);
            gbar(cnt);
            // out_part: 24 tasks, softmax-combine prologue
            if (bid < 24) stage_partF(bid % 3, bid / 3, nullptr, nullptr,
                                      nullptr, nullptr, 0, 0, 0, 0, nullptr,
                                      out_W + (size_t)l * D * D, Pout, D, D, 8, NORM_NONE,
                                      nullptr, nullptr, attA, attM, attL, SRC_ATT,
                                      xs, Asl, red);
            gbar(cnt);
            // ff1_part: 96 tasks, full-fold out_fin + residual xvA -> WB xvB, LN2
            if (bid < 96) stage_partF(bid % 12, bid / 12, nullptr, xvA,
                                      Pout, out_b + l * D, 8, D, 1, 0, xvB,
                                      ff1_W + (size_t)l * D * DFF, Pff1, DFF, D, 8, NORM_LN,
                                      ln2_g + l * D, ln2_b + l * D,
                                      nullptr, nullptr, nullptr, SRC_FOLD,
                                      xs, Asl, red);
            gbar(cnt);
            // ff2_part: 48 tasks, slice-fold ff1_fin + relu
            if (bid < 48) stage_partF(bid % 3, bid / 3, nullptr, nullptr,
                                      Pff1, ff1_b + l * DFF, 8, DFF, 0, 1, nullptr,
                                      ff2_W + (size_t)l * DFF * D, Pff2, D, DFF, 16, NORM_NONE,
                                      nullptr, nullptr, nullptr, nullptr, nullptr, SRC_FOLD,
                                      xs, Asl, red);
            gbar(cnt);
        }
    }
}

// ------------------------- host orchestration -------------------------
extern "C" void kernel_launch(void* const* d_in, const int* in_sizes, int n_in,
                              void* d_out, int out_size) {
    const float* feats    = (const float*)d_in[0];
    const float* past     = (const float*)d_in[1];
    const int*   intent   = (const int*)  d_in[2];
    const float* img_pos  = (const float*)d_in[3];
    const float* time_emb = (const float*)d_in[4];
    const float* int_emb  = (const float*)d_in[5];
    const float* past_W   = (const float*)d_in[6];
    const float* past_b   = (const float*)d_in[7];
    const float* pos_W    = (const float*)d_in[8];
    const float* pos_b    = (const float*)d_in[9];
    const float* ln1_g    = (const float*)d_in[10];
    const float* ln1_b    = (const float*)d_in[11];
    const float* qkv_W    = (const float*)d_in[12];
    const float* qkv_b    = (const float*)d_in[13];
    const float* out_W    = (const float*)d_in[14];
    const float* out_b    = (const float*)d_in[15];
    const float* ln2_g    = (const float*)d_in[16];
    const float* ln2_b    = (const float*)d_in[17];
    const float* ff1_W    = (const float*)d_in[18];
    const float* ff1_b    = (const float*)d_in[19];
    const float* ff2_W    = (const float*)d_in[20];
    const float* ff2_b    = (const float*)d_in[21];
    const float* dec1_W   = (const float*)d_in[22];
    const float* dec1_b   = (const float*)d_in[23];
    const float* dec2_W   = (const float*)d_in[24];
    const float* dec2_b   = (const float*)d_in[25];
    float* out = (float*)d_out;

    float *px, *ph, *pqkv, *pff, *pctx, *pK, *pV, *pxvA, *pxvB;
    float *pPdec1, *pPqkv, *pPout, *pPff1, *pPff2;
    float *pattA, *pattM, *pattL;
    cudaGetSymbolAddress((void**)&px,    g_x);
    cudaGetSymbolAddress((void**)&ph,    g_h);
    cudaGetSymbolAddress((void**)&pqkv,  g_qkv);
    cudaGetSymbolAddress((void**)&pff,   g_ff);
    cudaGetSymbolAddress((void**)&pctx,  g_ctx);
    cudaGetSymbolAddress((void**)&pK,    g_K);
    cudaGetSymbolAddress((void**)&pV,    g_V);
    cudaGetSymbolAddress((void**)&pxvA,  g_xvecA);
    cudaGetSymbolAddress((void**)&pxvB,  g_xvecB);
    cudaGetSymbolAddress((void**)&pPdec1, g_Pdec1);
    cudaGetSymbolAddress((void**)&pPqkv,  g_Pqkv);
    cudaGetSymbolAddress((void**)&pPout,  g_Pout);
    cudaGetSymbolAddress((void**)&pPff1,  g_Pff1);
    cudaGetSymbolAddress((void**)&pPff2,  g_Pff2);
    cudaGetSymbolAddress((void**)&pattA, g_attA);
    cudaGetSymbolAddress((void**)&pattM, g_attM);
    cudaGetSymbolAddress((void**)&pattL, g_attL);

    const int MB = (M0 + TM - 1) / TM;  // 17

    // ---- embed ----
    {
        int n = B * S0 * D;
        embed_kernel<<<(n + 255) / 256, 256>>>(feats, img_pos, intent, int_emb,
                                               past, past_W, past_b, time_emb, px);
    }

    // ---- prefill: 3 layers (tf32 DB tensor-core GEMMs, R15-proven) ----
    for (int l = 0; l < L; l++) {
        float* KcL = pK + (size_t)l * CACHE_L;
        float* VcL = pV + (size_t)l * CACHE_L;

        ln_kernel<<<M0, 256>>>(px, ph, ln1_g + l * D, ln1_b + l * D);
        gemm_kernel<<<dim3(D3 / TN, MB), 256>>>(
            ph, qkv_W + (size_t)l * D * D3, qkv_b + l * D3, nullptr, pqkv, M0, D3, D, 0);
        {
            int n = B * S0 * D;
            scatter_kv<<<(n + 255) / 256, 256>>>(pqkv, KcL, VcL);
        }
        attn_prefill<<<dim3((S0 + 3) / 4, B * H), 128>>>(pqkv, KcL, VcL, pctx);
        gemm_kernel<<<dim3(D / TN, MB), 256>>>(
            pctx, out_W + (size_t)l * D * D, out_b + l * D, px, px, M0, D, D, 0);
        ln_kernel<<<M0, 256>>>(px, ph, ln2_g + l * D, ln2_b + l * D);
        gemm_kernel<<<dim3(DFF / TN, MB), 256>>>(
            ph, ff1_W + (size_t)l * D * DFF, ff1_b + l * DFF, nullptr, pff, M0, DFF, D, 1);
        gemm_kernel<<<dim3(D / TN, MB), 256>>>(
            pff, ff2_W + (size_t)l * DFF * D, ff2_b + l * D, px, px, M0, D, DFF, 0);
    }

    copy_last<<<(B * D + 255) / 256, 256>>>(px, pxvA);

    // ---- decode: persistent megakernel, 17 stages/step ----
    int nsm = 0;
    cudaDeviceGetAttribute(&nsm, cudaDevAttrMultiProcessorCount, 0);
    int nb = nsm < 148 ? nsm : 148;
    if (nb < 128) nb = 128;

    reset_bar_kernel<<<1, 1>>>();
    decode_mega<<<nb, 256>>>(
        qkv_W, qkv_b, out_W, out_b, ff1_W, ff1_b, ff2_W, ff2_b,
        ln1_g, ln1_b, ln2_g, ln2_b,
        dec1_W, dec1_b, dec2_W, dec2_b,
        pos_W, pos_b, time_emb,
        pxvA, pxvB,
        pPdec1, pPqkv, pPout, pPff1, pPff2,
        pK, pV, pattA, pattM, pattL, out);
}